// round 12
// baseline (speedup 1.0000x reference)
#include <cuda_runtime.h>
#include <cuda_bf16.h>
#include <math.h>
#include <stdint.h>

#define NN    8192
#define SS    24
#define CC    4
#define EE    65536
#define TE    (EE+NN)
#define WINL  20
#define NWIN  4
#define YC    128
#define FLAT  2560
#define PROJ  1280
#define HID   128
#define GATE  512
#define NB    (NN*NWIN)
#define LBL   12

// ================= PTX helpers (sm_100 base ISA only) =================
__device__ __forceinline__ uint32_t smem_to_u32(const void* p) {
    uint32_t a;
    asm("{ .reg .u64 t; cvta.to.shared.u64 t, %1; cvt.u32.u64 %0, t; }" : "=r"(a) : "l"(p));
    return a;
}
__device__ __forceinline__ void cp_async16(uint32_t s, const void* g) {
    asm volatile("cp.async.cg.shared.global [%0], [%1], 16;" :: "r"(s), "l"(g));
}
__device__ __forceinline__ void cp_commit() { asm volatile("cp.async.commit_group;" ::: "memory"); }
template<int W> __device__ __forceinline__ void cp_wait() {
    asm volatile("cp.async.wait_group %0;" :: "n"(W) : "memory");
}
__device__ __forceinline__ void ldsm_x4(uint32_t* r, uint32_t a) {
    asm volatile("ldmatrix.sync.aligned.m8n8.x4.shared.b16 {%0,%1,%2,%3}, [%4];"
        : "=r"(r[0]), "=r"(r[1]), "=r"(r[2]), "=r"(r[3]) : "r"(a));
}
__device__ __forceinline__ void mma16816(float* c, const uint32_t* a, const uint32_t* b) {
    asm volatile("mma.sync.aligned.m16n8k16.row.col.f32.bf16.bf16.f32 "
        "{%0,%1,%2,%3}, {%4,%5,%6,%7}, {%8,%9}, {%0,%1,%2,%3};"
        : "+f"(c[0]), "+f"(c[1]), "+f"(c[2]), "+f"(c[3])
        : "r"(a[0]), "r"(a[1]), "r"(a[2]), "r"(a[3]), "r"(b[0]), "r"(b[1]));
}
#define SW128(off) ((off) ^ (((off) >> 3) & 0x70))
__device__ __forceinline__ uint32_t pack_bf2(float a, float b) {
    __nv_bfloat162 v = __floats2bfloat162_rn(a, b);
    return *(uint32_t*)&v;
}

// ---------------- scratch ----------------
__device__ __align__(256) float g_deg[NN];
__device__ __align__(256) int   g_cnt[NN];
__device__ __align__(256) int   g_rowptr[NN+1];
__device__ __align__(256) int   g_cursor[NN];
__device__ __align__(256) int   g_esrc[TE];
__device__ __align__(256) float g_enorm[TE];
__device__ __align__(256) float g_dinv[NN];
__device__ __align__(256) float g_agg[NN*SS*64];
__device__ __align__(256) float g_xA[NN*SS*128];
__device__ __align__(256) float g_xB[NN*SS*128];
__device__ __align__(256) __nv_bfloat16 g_Ahi[(size_t)NB*FLAT];
__device__ __align__(256) __nv_bfloat16 g_Alo[(size_t)NB*FLAT];
__device__ __align__(256) __nv_bfloat16 g_Bhi[(size_t)GATE*FLAT];   // Mt^T hi [j][k]
__device__ __align__(256) __nv_bfloat16 g_Blo[(size_t)GATE*FLAT];
__device__ __align__(256) __nv_bfloat16 g_pwh[(size_t)FLAT*PROJ];   // pw^T hi [k][p]
__device__ __align__(256) __nv_bfloat16 g_pwl[(size_t)FLAT*PROJ];
__device__ __align__(256) __nv_bfloat16 g_wihh[(size_t)GATE*PROJ];  // wih hi [j][p]
__device__ __align__(256) __nv_bfloat16 g_wihl[(size_t)GATE*PROJ];
__device__ __align__(256) __nv_bfloat16 g_whhh[GATE*HID];
__device__ __align__(256) __nv_bfloat16 g_whhl[GATE*HID];
__device__ __align__(256) __nv_bfloat16 g_hh[NN*HID];
__device__ __align__(256) __nv_bfloat16 g_hl[NN*HID];
__device__ __align__(256) float g_fb[GATE];
__device__ __align__(256) float g_gates[(size_t)NB*GATE];
__device__ __align__(256) float g_gbuf[NN*GATE];
__device__ __align__(256) float g_h[NN*HID];
__device__ __align__(256) float g_c[NN*HID];

// ---------------- operand pre-splitting ----------------
__global__ void __launch_bounds__(256) k_pw_split(const float* __restrict__ pw) {
    __shared__ float tile[32][65];
    int k0 = blockIdx.x * 64;
    int p0 = blockIdx.y * 32;
    int tid = threadIdx.x;
    for (int u = tid; u < 512; u += 256) {
        int r = u >> 4, c4 = u & 15;
        float4 v = *(const float4*)(pw + (size_t)(p0+r)*FLAT + k0 + c4*4);
        tile[r][c4*4+0] = v.x; tile[r][c4*4+1] = v.y;
        tile[r][c4*4+2] = v.z; tile[r][c4*4+3] = v.w;
    }
    __syncthreads();
    for (int u = tid; u < 1024; u += 256) {
        int kr = u >> 4, pc = u & 15;
        float a = tile[pc*2][kr];
        float b = tile[pc*2+1][kr];
        float ha = __bfloat162float(__float2bfloat16(a));
        float hb = __bfloat162float(__float2bfloat16(b));
        size_t off = (size_t)(k0+kr)*PROJ + p0 + pc*2;
        *(uint32_t*)(g_pwh + off) = pack_bf2(ha, hb);
        *(uint32_t*)(g_pwl + off) = pack_bf2(a - ha, b - hb);
    }
}

__global__ void k_wih_split(const float* __restrict__ wih) {
    int i4 = blockIdx.x*256 + threadIdx.x;
    float4 v = ((const float4*)wih)[i4];
    float hx = __bfloat162float(__float2bfloat16(v.x));
    float hy = __bfloat162float(__float2bfloat16(v.y));
    float hz = __bfloat162float(__float2bfloat16(v.z));
    float hw = __bfloat162float(__float2bfloat16(v.w));
    ((uint2*)g_wihh)[i4] = make_uint2(pack_bf2(hx, hy), pack_bf2(hz, hw));
    ((uint2*)g_wihl)[i4] = make_uint2(pack_bf2(v.x-hx, v.y-hy), pack_bf2(v.z-hz, v.w-hw));
}

__global__ void k_whh_split(const float* __restrict__ whh) {
    int i4 = blockIdx.x*256 + threadIdx.x;
    float4 v = ((const float4*)whh)[i4];
    float hx = __bfloat162float(__float2bfloat16(v.x));
    float hy = __bfloat162float(__float2bfloat16(v.y));
    float hz = __bfloat162float(__float2bfloat16(v.z));
    float hw = __bfloat162float(__float2bfloat16(v.w));
    ((uint2*)g_whhh)[i4] = make_uint2(pack_bf2(hx, hy), pack_bf2(hz, hw));
    ((uint2*)g_whhl)[i4] = make_uint2(pack_bf2(v.x-hx, v.y-hy), pack_bf2(v.z-hz, v.w-hw));
}

// ------- fused weight: pure HMMA GEMM (measured 56us) -------
#define MT_KC    64
#define MT_AH    0
#define MT_AL    8192
#define MT_BH    16384
#define MT_BL    32768
#define MT_ST    49152
#define MT_SMEM  (3*MT_ST)

__device__ __forceinline__ void mt_load_stage(uint32_t sbase, int j0, int k0, int pt, int tid) {
#pragma unroll
    for (int h = 0; h < 2; h++) {
        int u = tid + h*256; int r = u >> 3, c = u & 7;
        uint32_t so = sbase + MT_AH + SW128(r*128 + c*16);
        cp_async16(so, (const char*)g_wihh + ((size_t)(j0+r)*PROJ + pt)*2 + c*16);
    }
#pragma unroll
    for (int h = 0; h < 2; h++) {
        int u = tid + h*256; int r = u >> 3, c = u & 7;
        uint32_t so = sbase + MT_AL + SW128(r*128 + c*16);
        cp_async16(so, (const char*)g_wihl + ((size_t)(j0+r)*PROJ + pt)*2 + c*16);
    }
#pragma unroll
    for (int h = 0; h < 4; h++) {
        int u = tid + h*256; int r = u >> 3, c = u & 7;
        uint32_t so = sbase + MT_BH + SW128(r*128 + c*16);
        cp_async16(so, (const char*)g_pwh + ((size_t)(k0+r)*PROJ + pt)*2 + c*16);
    }
#pragma unroll
    for (int h = 0; h < 4; h++) {
        int u = tid + h*256; int r = u >> 3, c = u & 7;
        uint32_t so = sbase + MT_BL + SW128(r*128 + c*16);
        cp_async16(so, (const char*)g_pwl + ((size_t)(k0+r)*PROJ + pt)*2 + c*16);
    }
}

__global__ void __launch_bounds__(256, 1) k_mt_mma() {
    extern __shared__ __align__(1024) char smem[];
    const uint32_t smem_u = smem_to_u32(smem);
    const int tid = threadIdx.x, wid = tid >> 5, lane = tid & 31;
    const int k0 = blockIdx.x * 128;
    const int j0 = blockIdx.y * 64;

    const int wm = (wid >> 2) * 32;
    const int wn = (wid & 3) * 32;
    const int a_m  = (lane & 15);
    const int a_kh = (lane >> 4) * 16;
    const int b_n  = (lane & 7) + ((lane >> 4) & 1) * 8;
    const int b_kh = ((lane >> 3) & 1) * 16;

    float acc[2][4][4];
#pragma unroll
    for (int mt = 0; mt < 2; mt++)
#pragma unroll
        for (int nt = 0; nt < 4; nt++)
#pragma unroll
            for (int q = 0; q < 4; q++) acc[mt][nt][q] = 0.f;

    mt_load_stage(smem_u,           j0, k0, 0,       tid); cp_commit();
    mt_load_stage(smem_u + MT_ST,   j0, k0, MT_KC,   tid); cp_commit();
    mt_load_stage(smem_u + 2*MT_ST, j0, k0, 2*MT_KC, tid); cp_commit();

    const int NCH = PROJ / MT_KC;
    int buf = 0;
    for (int i = 0; i < NCH; i++) {
        cp_wait<2>();
        __syncthreads();
        const uint32_t sb = smem_u + buf * MT_ST;
#pragma unroll
        for (int kk = 0; kk < 4; kk++) {
            const int kb = kk * 32;
            uint32_t ah[2][4], al[2][4];
#pragma unroll
            for (int mt = 0; mt < 2; mt++) {
                int m = wm + mt*16 + a_m;
                uint32_t off = SW128(m*128 + kb + a_kh);
                ldsm_x4(ah[mt], sb + MT_AH + off);
                ldsm_x4(al[mt], sb + MT_AL + off);
            }
            uint32_t bh[2][4], bl[2][4];
#pragma unroll
            for (int p = 0; p < 2; p++) {
                int n = wn + p*16 + b_n;
                uint32_t off = SW128(n*128 + kb + b_kh);
                ldsm_x4(bh[p], sb + MT_BH + off);
                ldsm_x4(bl[p], sb + MT_BL + off);
            }
#pragma unroll
            for (int mt = 0; mt < 2; mt++)
#pragma unroll
                for (int nt = 0; nt < 4; nt++) {
                    const uint32_t* pbh = &bh[nt >> 1][(nt & 1) * 2];
                    const uint32_t* pbl = &bl[nt >> 1][(nt & 1) * 2];
                    mma16816(acc[mt][nt], ah[mt], pbh);
                    mma16816(acc[mt][nt], ah[mt], pbl);
                    mma16816(acc[mt][nt], al[mt], pbh);
                }
        }
        __syncthreads();
        if (i + 3 < NCH) mt_load_stage(smem_u + buf * MT_ST, j0, k0, (i + 3) * MT_KC, tid);
        cp_commit();
        buf = (buf + 1 == 3) ? 0 : buf + 1;
    }

    const int em = (lane >> 2);
    const int en = (lane & 3) * 2;
#pragma unroll
    for (int mt = 0; mt < 2; mt++)
#pragma unroll
        for (int nt = 0; nt < 4; nt++) {
            int col = k0 + wn + nt*8 + en;
#pragma unroll
            for (int half = 0; half < 2; half++) {
                int m = j0 + wm + mt*16 + em + half*8;
                float a0 = acc[mt][nt][half*2 + 0];
                float a1 = acc[mt][nt][half*2 + 1];
                float h0 = __bfloat162float(__float2bfloat16(a0));
                float h1 = __bfloat162float(__float2bfloat16(a1));
                *(uint32_t*)(g_Bhi + (size_t)m*FLAT + col) = pack_bf2(h0, h1);
                *(uint32_t*)(g_Blo + (size_t)m*FLAT + col) = pack_bf2(a0-h0, a1-h1);
            }
        }
}

// ---------------- small inits / graph preprocessing ----------------
__global__ void k_init_graph() {
    int n = blockIdx.x*256 + threadIdx.x;
    if (n < NN) { g_deg[n] = 1.0f; g_cnt[n] = 1; }
}

__global__ void k_init_state() {
    int i = blockIdx.x*256 + threadIdx.x;
    if (i < NN*HID) {
        g_h[i] = 0.f; g_c[i] = 0.f;
        g_hh[i] = __float2bfloat16(0.f);
        g_hl[i] = __float2bfloat16(0.f);
    }
}

__global__ void k_edge(const int* __restrict__ ei, const float* __restrict__ ea) {
    int e = blockIdx.x*256 + threadIdx.x;
    if (e < EE) {
        int d = ei[EE + e];
        atomicAdd(&g_deg[d], ea[e]);
        atomicAdd(&g_cnt[d], 1);
    }
}

__global__ void k_scan() {
    __shared__ int sums[1024];
    int t = threadIdx.x;
    int loc[8]; int s = 0;
#pragma unroll
    for (int i = 0; i < 8; i++) { loc[i] = s; s += g_cnt[t*8 + i]; }
    sums[t] = s;
    __syncthreads();
    for (int off = 1; off < 1024; off <<= 1) {
        int v = sums[t];
        int add = (t >= off) ? sums[t - off] : 0;
        __syncthreads();
        sums[t] = v + add;
        __syncthreads();
    }
    int base = (t > 0) ? sums[t-1] : 0;
#pragma unroll
    for (int i = 0; i < 8; i++) {
        int rp = base + loc[i];
        g_rowptr[t*8 + i] = rp;
        g_cursor[t*8 + i] = rp;
    }
    if (t == 1023) g_rowptr[NN] = sums[1023];
#pragma unroll
    for (int i = 0; i < 8; i++) {
        float d = g_deg[t*8 + i];
        g_dinv[t*8 + i] = (d > 0.f) ? rsqrtf(d) : 0.f;
    }
}

__global__ void k_scatter(const int* __restrict__ ei, const float* __restrict__ ea) {
    int e = blockIdx.x*256 + threadIdx.x;
    if (e < TE) {
        int s, d; float w;
        if (e < EE) { s = ei[e]; d = ei[EE + e]; w = ea[e]; }
        else        { s = d = e - EE; w = 1.0f; }
        int pos = atomicAdd(&g_cursor[d], 1);
        g_esrc[pos]  = s;
        g_enorm[pos] = g_dinv[s] * w * g_dinv[d];
    }
}

// ---------------- GCN ----------------
__global__ void k_spmm(const float* __restrict__ xin, int sel, int L4) {
    const float4* x = (sel == 0) ? (const float4*)xin
                     : (sel == 1) ? (const float4*)g_xA : (const float4*)g_xB;
    int gid = blockIdx.x*256 + threadIdx.x;
    if (gid >= NN * L4) return;
    int n = gid / L4;
    int v = gid - n*L4;
    int e0 = g_rowptr[n], e1 = g_rowptr[n+1];
    float ax = 0.f, ay = 0.f, az = 0.f, aw = 0.f;
    for (int e = e0; e < e1; e++) {
        float w = g_enorm[e];
        int   s = g_esrc[e];
        float4 xv = x[(size_t)s*L4 + v];
        ax += w*xv.x; ay += w*xv.y; az += w*xv.z; aw += w*xv.w;
    }
    ((float4*)g_agg)[gid] = make_float4(ax, ay, az, aw);
}

template<int FI, int FO, int SELO>
__global__ void __launch_bounds__(256) k_gcn(const float* __restrict__ W, const float* __restrict__ b) {
    float* xo = (SELO == 1) ? g_xA : g_xB;
    __shared__ float Ws[FI*FO];
    __shared__ float As[32*FI];
    __shared__ float bs[FO];
    int tid = threadIdx.x;
    int r0 = blockIdx.x * 32;
    for (int i = tid; i < FI*FO; i += 256) { int o = i / FI, c = i - o*FI; Ws[c*FO + o] = W[i]; }
    for (int i = tid; i < FO; i += 256) bs[i] = b[i];
    for (int i = tid; i < 32*FI; i += 256) As[i] = g_agg[(size_t)r0*FI + i];
    __syncthreads();
    const int CG = FO / 2;
    for (int u = tid; u < 8*CG; u += 256) {
        int rg = u / CG; int cg = u - rg*CG;
        int r = rg*4, o = cg*2;
        float a00=0,a01=0,a10=0,a11=0,a20=0,a21=0,a30=0,a31=0;
#pragma unroll
        for (int c = 0; c < FI; c++) {
            float w0 = Ws[c*FO + o], w1 = Ws[c*FO + o + 1];
            float x0 = As[(r+0)*FI + c], x1 = As[(r+1)*FI + c];
            float x2 = As[(r+2)*FI + c], x3 = As[(r+3)*FI + c];
            a00 += x0*w0; a01 += x0*w1;
            a10 += x1*w0; a11 += x1*w1;
            a20 += x2*w0; a21 += x2*w1;
            a30 += x3*w0; a31 += x3*w1;
        }
        float* p0 = xo + (size_t)(r0+r  )*FO;
        float* p1 = xo + (size_t)(r0+r+1)*FO;
        float* p2 = xo + (size_t)(r0+r+2)*FO;
        float* p3 = xo + (size_t)(r0+r+3)*FO;
        p0[o] = tanhf(a00 + bs[o]); p0[o+1] = tanhf(a01 + bs[o+1]);
        p1[o] = tanhf(a10 + bs[o]); p1[o+1] = tanhf(a11 + bs[o+1]);
        p2[o] = tanhf(a20 + bs[o]); p2[o+1] = tanhf(a21 + bs[o+1]);
        p3[o] = tanhf(a30 + bs[o]); p3[o+1] = tanhf(a31 + bs[o+1]);
    }
}

// HMMA transform for big layers (FI 32/64)
template<int FI, int FO, int SELO>
__global__ void __launch_bounds__(256) k_gcn_mma(const float* __restrict__ W, const float* __restrict__ b) {
    float* xo = (SELO == 1) ? g_xA : g_xB;
    extern __shared__ __align__(1024) char smem[];
    const int SA = 128*128;
    const int SB = FO*128;
    const uint32_t uAH = smem_to_u32(smem);
    const uint32_t uAL = uAH + SA;
    const uint32_t uBH = uAH + 2*SA;
    const uint32_t uBL = uAH + 2*SA + SB;
    float* pb = (float*)(smem + 2*SA + 2*SB);
    const int tid = threadIdx.x, wid = tid >> 5, lane = tid & 31;
    const int r0 = blockIdx.x * 128;

    for (int idx = tid; idx < 128*FI/4; idx += 256) {
        int r  = idx / (FI/4);
        int c4 = idx % (FI/4);
        float4 v = *(const float4*)(g_agg + (size_t)(r0+r)*FI + c4*4);
        uint32_t sw = (uint32_t)(r*128 + c4*8) ^ ((uint32_t)(r & 7) << 4);
        float hx = __bfloat162float(__float2bfloat16(v.x));
        float hy = __bfloat162float(__float2bfloat16(v.y));
        float hz = __bfloat162float(__float2bfloat16(v.z));
        float hw = __bfloat162float(__float2bfloat16(v.w));
        *(uint32_t*)((char*)smem + sw)            = pack_bf2(hx, hy);
        *(uint32_t*)((char*)smem + sw + 4)        = pack_bf2(hz, hw);
        *(uint32_t*)((char*)smem + SA + sw)       = pack_bf2(v.x - hx, v.y - hy);
        *(uint32_t*)((char*)smem + SA + sw + 4)   = pack_bf2(v.z - hz, v.w - hw);
    }
    for (int idx = tid; idx < FO*FI/4; idx += 256) {
        int r  = idx / (FI/4);
        int c4 = idx % (FI/4);
        float4 v = *(const float4*)(W + (size_t)r*FI + c4*4);
        uint32_t sw = (uint32_t)(r*128 + c4*8) ^ ((uint32_t)(r & 7) << 4);
        float hx = __bfloat162float(__float2bfloat16(v.x));
        float hy = __bfloat162float(__float2bfloat16(v.y));
        float hz = __bfloat162float(__float2bfloat16(v.z));
        float hw = __bfloat162float(__float2bfloat16(v.w));
        *(uint32_t*)((char*)smem + 2*SA + sw)          = pack_bf2(hx, hy);
        *(uint32_t*)((char*)smem + 2*SA + sw + 4)      = pack_bf2(hz, hw);
        *(uint32_t*)((char*)smem + 2*SA + SB + sw)     = pack_bf2(v.x - hx, v.y - hy);
        *(uint32_t*)((char*)smem + 2*SA + SB + sw + 4) = pack_bf2(v.z - hz, v.w - hw);
    }
    for (int i = tid; i < FO; i += 256) pb[i] = b[i];
    __syncthreads();

    constexpr int NT  = (FO == 128) ? 8 : 4;
    constexpr int NPT = NT / 2;
    const int wm = (wid >> 1) * 32;
    const int wn = (wid & 1) * (FO / 2);
    const int a_m  = (lane & 15);
    const int a_kh = (lane >> 4) * 16;
    const int b_n  = (lane & 7) + ((lane >> 4) & 1) * 8;
    const int b_kh = ((lane >> 3) & 1) * 16;

    float acc[2][NT][4];
#pragma unroll
    for (int mt = 0; mt < 2; mt++)
#pragma unroll
        for (int nt = 0; nt < NT; nt++)
#pragma unroll
            for (int q = 0; q < 4; q++) acc[mt][nt][q] = 0.f;

#pragma unroll
    for (int kk = 0; kk < FI/16; kk++) {
        const int kb = kk * 32;
        uint32_t ah[2][4], al[2][4];
#pragma unroll
        for (int mt = 0; mt < 2; mt++) {
            int m = wm + mt*16 + a_m;
            uint32_t off = (uint32_t)(m*128 + kb + a_kh) ^ ((uint32_t)(m & 7) << 4);
            ldsm_x4(ah[mt], uAH + off);
            ldsm_x4(al[mt], uAL + off);
        }
        uint32_t bh[NPT][4], bl[NPT][4];
#pragma unroll
        for (int p = 0; p < NPT; p++) {
            int n = wn + p*16 + b_n;
            uint32_t off = (uint32_t)(n*128 + kb + b_kh) ^ ((uint32_t)(n & 7) << 4);
            ldsm_x4(bh[p], uBH + off);
            ldsm_x4(bl[p], uBL + off);
        }
#pragma unroll
        for (int mt = 0; mt < 2; mt++)
#pragma unroll
            for (int nt = 0; nt < NT; nt++) {
                const uint32_t* pbh = &bh[nt >> 1][(nt & 1) * 2];
                const uint32_t* pbl = &bl[nt >> 1][(nt & 1) * 2];
                mma16816(acc[mt][nt], ah[mt], pbh);
                mma16816(acc[mt][nt], ah[mt], pbl);
                mma16816(acc[mt][nt], al[mt], pbh);
            }
    }

    const int em = (lane >> 2);
    const int en = (lane & 3) * 2;
#pragma unroll
    for (int mt = 0; mt < 2; mt++)
#pragma unroll
        for (int nt = 0; nt < NT; nt++) {
            int col = wn + nt*8 + en;
            int m   = r0 + wm + mt*16 + em;
            float b0 = pb[col], b1 = pb[col+1];
            float2 v0 = make_float2(tanhf(acc[mt][nt][0] + b0), tanhf(acc[mt][nt][1] + b1));
            float2 v1 = make_float2(tanhf(acc[mt][nt][2] + b0), tanhf(acc[mt][nt][3] + b1));
            *(float2*)(xo + (size_t)m * FO + col)       = v0;
            *(float2*)(xo + (size_t)(m + 8) * FO + col) = v1;
        }
}

// ------- conv+pool: per-node scalar -------
__global__ void k_convpool(const float* __restrict__ cw, const float* __restrict__ cb) {
    __shared__ __align__(16) float xs[SS*YC];
    __shared__ float cws[10], cbs[2];
    int n = blockIdx.x;
    int tid = threadIdx.x;
    const float4* src = (const float4*)(g_xA + (size_t)n*SS*YC);
    for (int i = tid; i < SS*YC/4; i += 256) ((float4*)xs)[i] = src[i];
    if (tid < 10) cws[tid] = cw[tid];
    if (tid < 2)  cbs[tid] = cb[tid];
    __syncthreads();
#pragma unroll
    for (int w = 0; w < NWIN; w++) {
        const float* win = xs + w*YC;
        size_t obase = (size_t)(n*NWIN + w)*FLAT;
        for (int i = tid; i < FLAT; i += 256) {
            int f = i / 1280;
            int q = i - f*1280;
            int p0 = q*2;
            float v0 = cbs[f], v1 = cbs[f];
#pragma unroll
            for (int k = 0; k < 5; k++) {
                int p = p0 + k - 2;
                if (p >= 0 && p < FLAT) v0 += win[p] * cws[f*5 + k];
                p += 1;
                if (p >= 0 && p < FLAT) v1 += win[p] * cws[f*5 + k];
            }
            float v = fmaxf(v0, v1);
            __nv_bfloat16 h = __float2bfloat16(v);
            float lo = v - __bfloat162float(h);
            g_Ahi[obase + i] = h;
            g_Alo[obase + i] = __float2bfloat16(lo);
        }
    }
}

// ------- fused bias: one warp per output j -------
__global__ void __launch_bounds__(256) k_fb(const float* __restrict__ wih, const float* __restrict__ pb,
                     const float* __restrict__ bih, const float* __restrict__ bhh) {
    int wix = (blockIdx.x*256 + threadIdx.x) >> 5;
    int lane = threadIdx.x & 31;
    if (wix >= GATE) return;
    const float* row = wih + (size_t)wix*PROJ;
    float acc = 0.f;
#pragma unroll 8
    for (int p = lane; p < PROJ; p += 32) acc += row[p] * pb[p];
#pragma unroll
    for (int o = 16; o > 0; o >>= 1) acc += __shfl_xor_sync(0xFFFFFFFFu, acc, o);
    if (lane == 0) g_fb[wix] = acc + bih[wix] + bhh[wix];
}

// ============ gates GEMM: KC=32, 6-stage deep pipeline ============
// Tile layout: 128 rows x 32 k per stage array; two rows share one 128B line:
//   phys(r, kb) = (r & 63)*128 + (r >> 6)*64 + kb,  then SW128.
#define GK_KC    32
#define GK_NCH   (FLAT/GK_KC)     // 80
#define GK_NS    6
#define ST_AH    0
#define ST_AL    8192
#define ST_BH    16384
#define ST_BL    24576
#define ST_SIZE  32768
#define GK_SMEM  (GK_NS*ST_SIZE + 512)

__device__ __forceinline__ uint32_t gk_phys(int r, int kb) {
    return SW128((uint32_t)((r & 63)*128 + (r >> 6)*64 + kb));
}

__device__ __forceinline__ void gk_load_stage(uint32_t sbase, int m0, int j0, int kt, int tid) {
    const char* gbase[4] = {
        (const char*)g_Ahi, (const char*)g_Alo, (const char*)g_Bhi, (const char*)g_Blo };
    const int row0[4] = { m0, m0, j0, j0 };
#pragma unroll
    for (int h = 0; h < 8; h++) {          // 4 tiles x 512 chunks / 256 threads
        int tile = h >> 1;
        int u    = tid + (h & 1) * 256;    // 0..511
        int r    = u >> 2;
        int c    = u & 3;
        uint32_t so = sbase + tile*8192 + gk_phys(r, c*16);
        const char* gp = gbase[tile] + ((size_t)(row0[tile] + r) * FLAT + kt) * 2 + c*16;
        cp_async16(so, gp);
    }
}

__global__ void __launch_bounds__(256, 1) k_gates_hmma() {
    extern __shared__ __align__(1024) char smem[];
    const uint32_t smem_u = smem_to_u32(smem);
    float* fbs = (float*)(smem + GK_NS*ST_SIZE);
    const int tid = threadIdx.x;
    const int wid = tid >> 5;
    const int lane = tid & 31;
    const int j0 = blockIdx.x * 128;
    const int m0 = blockIdx.y * 128;
    const int wm = (wid >> 1) * 32;
    const int wn = (wid & 1) * 64;

    if (tid < 128) fbs[tid] = g_fb[j0 + tid];

    float acc[2][8][4];
#pragma unroll
    for (int mt = 0; mt < 2; mt++)
#pragma unroll
        for (int nt = 0; nt < 8; nt++)
#pragma unroll
            for (int q = 0; q < 4; q++) acc[mt][nt][q] = 0.f;

    // prefetch 5 chunks (5 in flight, 6 buffers)
#pragma unroll
    for (int s = 0; s < 5; s++) {
        gk_load_stage(smem_u + s*ST_SIZE, m0, j0, s*GK_KC, tid);
        cp_commit();
    }

    const int a_m  = (lane & 15);
    const int a_kh = (lane >> 4) * 16;
    const int b_n  = (lane & 7) + ((lane >> 4) & 1) * 8;
    const int b_kh = ((lane >> 3) & 1) * 16;

    int buf = 0;
    for (int i = 0; i < GK_NCH; i++) {
        cp_wait<4>();
        __syncthreads();
        const uint32_t sb = smem_u + buf * ST_SIZE;

#pragma unroll
        for (int kk = 0; kk < 2; kk++) {
            const int kb = kk * 32;      // byte offset within 64B row (k16 = 32B)
            uint32_t ah[2][4], al[2][4];
#pragma unroll
            for (int mt = 0; mt < 2; mt++) {
                int m = wm + mt*16 + a_m;
                uint32_t off = gk_phys(m, kb + a_kh);
                ldsm_x4(ah[mt], sb + ST_AH + off);
                ldsm_x4(al[mt], sb + ST_AL + off);
            }
            uint32_t bh[4][4], bl[4][4];
#pragma unroll
            for (int p = 0; p < 4; p++) {
                int n = wn + p*16 + b_n;
                uint32_t off = gk_phys(n, kb + b_kh);
                ldsm_x4(bh[p], sb + ST_BH + off);
                ldsm_x4(bl[p], sb + ST_BL + off);
            }
#pragma unroll
            for (int mt = 0; mt < 2; mt++)
#pragma unroll
                for (int nt = 0; nt < 8; nt++) {
                    const uint32_t* pbh = &bh[nt >> 1][(nt & 1) * 2];
                    const uint32_t* pbl = &bl[nt >> 1][(nt & 1) * 2];
                    mma16816(acc[mt][nt], ah[mt], pbh);
                    mma16816(acc[mt][nt], ah[mt], pbl);
                    mma16816(acc[mt][nt], al[mt], pbh);
                }
        }
        __syncthreads();
        if (i + 5 < GK_NCH) {
            gk_load_stage(smem_u + ((i + 5) % GK_NS) * ST_SIZE, m0, j0, (i + 5) * GK_KC, tid);
        }
        cp_commit();
        buf = (buf + 1 == GK_NS) ? 0 : buf + 1;
    }

    const int em = (lane >> 2);
    const int en = (lane & 3) * 2;
#pragma unroll
    for (int mt = 0; mt < 2; mt++) {
#pragma unroll
        for (int nt = 0; nt < 8; nt++) {
            int nl = wn + nt*8 + en;
            int m  = m0 + wm + mt*16 + em;
            float f0 = fbs[nl], f1 = fbs[nl + 1];
            float2 v0 = make_float2(acc[mt][nt][0] + f0, acc[mt][nt][1] + f1);
            float2 v1 = make_float2(acc[mt][nt][2] + f0, acc[mt][nt][3] + f1);
            *(float2*)(g_gates + (size_t)m * GATE + j0 + nl)       = v0;
            *(float2*)(g_gates + (size_t)(m + 8) * GATE + j0 + nl) = v1;
        }
    }
}

// ---------------- LSTM: HMMA recurrent gemm ----------------
#define LG_SMEM (2*16384 + 2*32768)
__global__ void __launch_bounds__(256) k_lstm_mma(int t) {
    extern __shared__ __align__(1024) char smem[];
    const uint32_t uAH = smem_to_u32(smem);
    const uint32_t uAL = uAH + 16384;
    const uint32_t uBH = uAH + 32768;
    const uint32_t uBL = uAH + 65536;
    const int tid = threadIdx.x, wid = tid >> 5, lane = tid & 31;
    const int j0 = blockIdx.x * 128;
    const int n0 = blockIdx.y * 64;

    for (int u = tid; u < 1024; u += 256) {
        int r = u >> 4, c8 = u & 15;
        int row = r + 64*(c8 >> 3);
        uint32_t sw = (uint32_t)(row*128 + (c8 & 7)*16) ^ ((uint32_t)(row & 7) << 4);
        *(uint4*)((char*)smem + sw)         = *(const uint4*)(g_hh + (size_t)(n0+r)*HID + c8*8);
        *(uint4*)((char*)smem + 16384 + sw) = *(const uint4*)(g_hl + (size_t)(n0+r)*HID + c8*8);
    }
    for (int u = tid; u < 2048; u += 256) {
        int r = u >> 4, c8 = u & 15;
        int row = r + 128*(c8 >> 3);
        uint32_t sw = (uint32_t)(row*128 + (c8 & 7)*16) ^ ((uint32_t)(row & 7) << 4);
        *(uint4*)((char*)smem + 32768 + sw) = *(const uint4*)(g_whhh + (size_t)(j0+r)*HID + c8*8);
        *(uint4*)((char*)smem + 65536 + sw) = *(const uint4*)(g_whhl + (size_t)(j0+r)*HID + c8*8);
    }
    __syncthreads();

    const int wm = (wid >> 2) * 32;
    const int wn = (wid & 3) * 32;
    const int a_m  = (lane & 15);
    const int a_kh = (lane >> 4) * 16;
    const int b_n  = (lane & 7) + ((lane >> 4) & 1) * 8;
    const int b_kh = ((lane >> 3) & 1) * 16;

    float acc[2][4][4];
#pragma unroll
    for (int mt = 0; mt < 2; mt++)
#pragma unroll
        for (int nt = 0; nt < 4; nt++)
#pragma unroll
            for (int q = 0; q < 4; q++) acc[mt][nt][q] = 0.f;

#pragma unroll
    for (int kk = 0; kk < 8; kk++) {
        const int half = kk >> 2;
        const int kb = (kk & 3) * 32;
        uint32_t ah[2][4], al[2][4];
#pragma unroll
        for (int mt = 0; mt < 2; mt++) {
            int m = wm + mt*16 + a_m;
            int row = m + 64*half;
            uint32_t off = (uint32_t)(row*128 + kb + a_kh) ^ ((uint32_t)(row & 7) << 4);
            ldsm_x4(ah[mt], uAH + off);
            ldsm_x4(al[mt], uAL + off);
        }
        uint32_t bh[2][4], bl[2][4];
#pragma unroll
        for (int p = 0; p < 2; p++) {
            int nj = wn + p*16 + b_n;
            int row = nj + 128*half;
            uint32_t off = (uint32_t)(row*128 + kb + b_kh) ^ ((uint32_t)(row & 7) << 4);
            ldsm_x4(bh[p], uBH + off);
            ldsm_x4(bl[p], uBL + off);
        }
#pragma unroll
        for (int mt = 0; mt < 2; mt++)
#pragma unroll
            for (int nt = 0; nt < 4; nt++) {
                const uint32_t* pbh = &bh[nt >> 1][(nt & 1) * 2];
                const uint32_t* pbl = &bl[nt >> 1][(nt & 1) * 2];
                mma16816(acc[mt][nt], ah[mt], pbh);
                mma16816(acc[mt][nt], ah[mt], pbl);
                mma16816(acc[mt][nt], al[mt], pbh);
            }
    }

    const int em = (lane >> 2);
    const int en = (lane & 3) * 2;
#pragma unroll
    for (int mt = 0; mt < 2; mt++)
#pragma unroll
        for (int nt = 0; nt < 4; nt++) {
            int jj = j0 + wn + nt*8 + en;
#pragma unroll
            for (int half = 0; half < 2; half++) {
                int n = n0 + wm + mt*16 + em + half*8;
                float2 gx = *(const float2*)(g_gates + ((size_t)n*4 + t)*GATE + jj);
                float2 v = make_float2(acc[mt][nt][half*2+0] + gx.x,
                                       acc[mt][nt][half*2+1] + gx.y);
                *(float2*)(g_gbuf + (size_t)n*GATE + jj) = v;
            }
        }
}

__device__ __forceinline__ float sigf(float x) { return 1.0f / (1.0f + expf(-x)); }

__global__ void k_lstm_point() {
    int idx = blockIdx.x*256 + threadIdx.x;
    if (idx < NN*HID) {
        int n = idx >> 7, j = idx & 127;
        const float* g = g_gbuf + (size_t)n*GATE;
        float gi = g[j], gf = g[HID + j], gg = g[2*HID + j], go = g[3*HID + j];
        float c = sigf(gf) * g_c[idx] + sigf(gi) * tanhf(gg);
        g_c[idx] = c;
        float h = sigf(go) * tanhf(c);
        g_h[idx] = h;
        __nv_bfloat16 hb = __float2bfloat16(h);
        g_hh[idx] = hb;
        g_hl[idx] = __float2bfloat16(h - __bfloat162float(hb));
    }
}

// ---------------- output head ----------------
__global__ void k_out(const float* __restrict__ ow, const float* __restrict__ ob,
                      float* __restrict__ out) {
    int idx = blockIdx.x*256 + threadIdx.x;
    if (idx < NN*LBL) {
        int n = idx / LBL, l = idx - n*LBL;
        float acc = ob[l];
        const float* hr = g_h + (size_t)n*HID;
        const float* wr = ow + (size_t)l*HID;
#pragma unroll 8
        for (int k = 0; k < HID; k++) acc += hr[k]*wr[k];
        out[idx] = acc;
    }
}

// ---------------- launch ----------------
extern "C" void kernel_launch(void* const* d_in, const int* in_sizes, int n_in,
                              void* d_out, int out_size) {
    const float* inputs = (const float*)d_in[0];
    const int*   ei     = (const int*)  d_in[1];
    const float* ea     = (const float*)d_in[2];
    const float* W1 = (const float*)d_in[3];  const float* b1 = (const float*)d_in[4];
    const float* W2 = (const float*)d_in[5];  const float* b2 = (const float*)d_in[6];
    const float* W3 = (const float*)d_in[7];  const float* b3 = (const float*)d_in[8];
    const float* W4 = (const float*)d_in[9];  const float* b4 = (const float*)d_in[10];
    const float* W5 = (const float*)d_in[11]; const float* b5 = (const float*)d_in[12];
    const float* cw  = (const float*)d_in[13]; const float* cb  = (const float*)d_in[14];
    const float* pw  = (const float*)d_in[15]; const float* pb  = (const float*)d_in[16];
    const float* wih = (const float*)d_in[17]; const float* whh = (const float*)d_in[18];
    const float* bih = (const float*)d_in[19]; const float* bhh = (const float*)d_in[20];
    const float* ow  = (const float*)d_in[21]; const float* ob  = (const float*)d_in[22];
    float* out = (float*)d_out;

    const int SMEM_GCN4 = 2*16384 + 2*64*128  + 256;
    const int SMEM_GCN5 = 2*16384 + 2*128*128 + 512;
    cudaFuncSetAttribute(k_gates_hmma, cudaFuncAttributeMaxDynamicSharedMemorySize, GK_SMEM);
    cudaFuncSetAttribute(k_gcn_mma<32,64,2>,  cudaFuncAttributeMaxDynamicSharedMemorySize, SMEM_GCN4);
    cudaFuncSetAttribute(k_gcn_mma<64,128,1>, cudaFuncAttributeMaxDynamicSharedMemorySize, SMEM_GCN5);
    cudaFuncSetAttribute(k_mt_mma,  cudaFuncAttributeMaxDynamicSharedMemorySize, MT_SMEM);
    cudaFuncSetAttribute(k_lstm_mma, cudaFuncAttributeMaxDynamicSharedMemorySize, LG_SMEM);

    // operand splits first; k_mt_mma lands at launch #4 (ncu -s window)
    k_pw_split<<<dim3(FLAT/64, PROJ/32), 256>>>(pw);
    k_wih_split<<<GATE*PROJ/4/256, 256>>>(wih);
    k_whh_split<<<GATE*HID/4/256, 256>>>(whh);
    k_mt_mma<<<dim3(FLAT/128, GATE/64), 256, MT_SMEM>>>();
    k_fb<<<GATE/8, 256>>>(wih, pb, bih, bhh);

    k_init_graph<<<32, 256>>>();
    k_init_state<<<4096, 256>>>();

    // graph preprocessing
    k_edge<<<EE/256, 256>>>(ei, ea);
    k_scan<<<1, 1024>>>();
    k_scatter<<<(TE + 255)/256, 256>>>(ei, ea);

    // 5 GCN layers
    k_spmm<<<(NN*24  + 255)/256, 256>>>(inputs, 0, 24);
    k_gcn<4, 8, 1><<<6144, 256>>>(W1, b1);
    k_spmm<<<(NN*48  + 255)/256, 256>>>(nullptr, 1, 48);
    k_gcn<8, 16, 2><<<6144, 256>>>(W2, b2);
    k_spmm<<<(NN*96  + 255)/256, 256>>>(nullptr, 2, 96);
    k_gcn<16, 32, 1><<<6144, 256>>>(W3, b3);
    k_spmm<<<(NN*192 + 255)/256, 256>>>(nullptr, 1, 192);
    k_gcn_mma<32, 64, 2><<<1536, 256, SMEM_GCN4>>>(W4, b4);
    k_spmm<<<(NN*384 + 255)/256, 256>>>(nullptr, 2, 384);
    k_gcn_mma<64, 128, 1><<<1536, 256, SMEM_GCN5>>>(W5, b5);

    // conv + pool
    k_convpool<<<NN, 256>>>(cw, cb);

    // gates GEMM (deep pipeline)
    k_gates_hmma<<<dim3(4, 256), 256, GK_SMEM>>>();

    // LSTM
    for (int t = 0; t < NWIN; t++) {
        k_lstm_mma<<<dim3(4, 128), 256, LG_SMEM>>>(t);
        k_lstm_point<<<4096, 256>>>();
    }

    // output head
    k_out<<<(NN*LBL + 255)/256, 256>>>(ow, ob, out);
}

// round 13
// speedup vs baseline: 1.1166x; 1.1166x over previous
#include <cuda_runtime.h>
#include <cuda_bf16.h>
#include <math.h>
#include <stdint.h>

#define NN    8192
#define SS    24
#define CC    4
#define EE    65536
#define TE    (EE+NN)
#define WINL  20
#define NWIN  4
#define YC    128
#define FLAT  2560
#define PROJ  1280
#define HID   128
#define GATE  512
#define NB    (NN*NWIN)
#define LBL   12

// ================= PTX helpers (sm_100 base ISA only) =================
__device__ __forceinline__ uint32_t smem_to_u32(const void* p) {
    uint32_t a;
    asm("{ .reg .u64 t; cvta.to.shared.u64 t, %1; cvt.u32.u64 %0, t; }" : "=r"(a) : "l"(p));
    return a;
}
__device__ __forceinline__ void cp_async16(uint32_t s, const void* g) {
    asm volatile("cp.async.cg.shared.global [%0], [%1], 16;" :: "r"(s), "l"(g));
}
__device__ __forceinline__ void cp_commit() { asm volatile("cp.async.commit_group;" ::: "memory"); }
template<int W> __device__ __forceinline__ void cp_wait() {
    asm volatile("cp.async.wait_group %0;" :: "n"(W) : "memory");
}
__device__ __forceinline__ void ldsm_x4(uint32_t* r, uint32_t a) {
    asm volatile("ldmatrix.sync.aligned.m8n8.x4.shared.b16 {%0,%1,%2,%3}, [%4];"
        : "=r"(r[0]), "=r"(r[1]), "=r"(r[2]), "=r"(r[3]) : "r"(a));
}
__device__ __forceinline__ void mma16816(float* c, const uint32_t* a, const uint32_t* b) {
    asm volatile("mma.sync.aligned.m16n8k16.row.col.f32.bf16.bf16.f32 "
        "{%0,%1,%2,%3}, {%4,%5,%6,%7}, {%8,%9}, {%0,%1,%2,%3};"
        : "+f"(c[0]), "+f"(c[1]), "+f"(c[2]), "+f"(c[3])
        : "r"(a[0]), "r"(a[1]), "r"(a[2]), "r"(a[3]), "r"(b[0]), "r"(b[1]));
}
#define SW128(off) ((off) ^ (((off) >> 3) & 0x70))
__device__ __forceinline__ uint32_t pack_bf2(float a, float b) {
    __nv_bfloat162 v = __floats2bfloat162_rn(a, b);
    return *(uint32_t*)&v;
}

// ---------------- scratch ----------------
__device__ __align__(256) float g_deg[NN];
__device__ __align__(256) int   g_cnt[NN];
__device__ __align__(256) int   g_rowptr[NN+1];
__device__ __align__(256) int   g_cursor[NN];
__device__ __align__(256) int   g_esrc[TE];
__device__ __align__(256) float g_enorm[TE];
__device__ __align__(256) float g_dinv[NN];
__device__ __align__(256) float g_agg[NN*SS*64];
__device__ __align__(256) float g_xA[NN*SS*128];
__device__ __align__(256) float g_xB[NN*SS*128];
__device__ __align__(256) __nv_bfloat16 g_Ahi[(size_t)NB*FLAT];
__device__ __align__(256) __nv_bfloat16 g_Alo[(size_t)NB*FLAT];
__device__ __align__(256) __nv_bfloat16 g_Bhi[(size_t)GATE*FLAT];   // Mt^T hi [j][k]
__device__ __align__(256) __nv_bfloat16 g_Blo[(size_t)GATE*FLAT];
__device__ __align__(256) __nv_bfloat16 g_pwh[(size_t)FLAT*PROJ];   // pw^T hi [k][p]
__device__ __align__(256) __nv_bfloat16 g_pwl[(size_t)FLAT*PROJ];
__device__ __align__(256) __nv_bfloat16 g_wihh[(size_t)GATE*PROJ];  // wih hi [j][p]
__device__ __align__(256) __nv_bfloat16 g_wihl[(size_t)GATE*PROJ];
__device__ __align__(256) __nv_bfloat16 g_whhh[GATE*HID];
__device__ __align__(256) __nv_bfloat16 g_whhl[GATE*HID];
__device__ __align__(256) __nv_bfloat16 g_hh[NN*HID];
__device__ __align__(256) __nv_bfloat16 g_hl[NN*HID];
__device__ __align__(256) float g_fb[GATE];
__device__ __align__(256) float g_gates[(size_t)NB*GATE];
__device__ __align__(256) float g_gbuf[NN*GATE];
__device__ __align__(256) float g_h[NN*HID];
__device__ __align__(256) float g_c[NN*HID];

// ---------------- operand pre-splitting ----------------
__global__ void __launch_bounds__(256) k_pw_split(const float* __restrict__ pw) {
    __shared__ float tile[32][65];
    int k0 = blockIdx.x * 64;
    int p0 = blockIdx.y * 32;
    int tid = threadIdx.x;
    for (int u = tid; u < 512; u += 256) {
        int r = u >> 4, c4 = u & 15;
        float4 v = *(const float4*)(pw + (size_t)(p0+r)*FLAT + k0 + c4*4);
        tile[r][c4*4+0] = v.x; tile[r][c4*4+1] = v.y;
        tile[r][c4*4+2] = v.z; tile[r][c4*4+3] = v.w;
    }
    __syncthreads();
    for (int u = tid; u < 1024; u += 256) {
        int kr = u >> 4, pc = u & 15;
        float a = tile[pc*2][kr];
        float b = tile[pc*2+1][kr];
        float ha = __bfloat162float(__float2bfloat16(a));
        float hb = __bfloat162float(__float2bfloat16(b));
        size_t off = (size_t)(k0+kr)*PROJ + p0 + pc*2;
        *(uint32_t*)(g_pwh + off) = pack_bf2(ha, hb);
        *(uint32_t*)(g_pwl + off) = pack_bf2(a - ha, b - hb);
    }
}

__global__ void k_wih_split(const float* __restrict__ wih) {
    int i4 = blockIdx.x*256 + threadIdx.x;
    float4 v = ((const float4*)wih)[i4];
    float hx = __bfloat162float(__float2bfloat16(v.x));
    float hy = __bfloat162float(__float2bfloat16(v.y));
    float hz = __bfloat162float(__float2bfloat16(v.z));
    float hw = __bfloat162float(__float2bfloat16(v.w));
    ((uint2*)g_wihh)[i4] = make_uint2(pack_bf2(hx, hy), pack_bf2(hz, hw));
    ((uint2*)g_wihl)[i4] = make_uint2(pack_bf2(v.x-hx, v.y-hy), pack_bf2(v.z-hz, v.w-hw));
}

__global__ void k_whh_split(const float* __restrict__ whh) {
    int i4 = blockIdx.x*256 + threadIdx.x;
    float4 v = ((const float4*)whh)[i4];
    float hx = __bfloat162float(__float2bfloat16(v.x));
    float hy = __bfloat162float(__float2bfloat16(v.y));
    float hz = __bfloat162float(__float2bfloat16(v.z));
    float hw = __bfloat162float(__float2bfloat16(v.w));
    ((uint2*)g_whhh)[i4] = make_uint2(pack_bf2(hx, hy), pack_bf2(hz, hw));
    ((uint2*)g_whhl)[i4] = make_uint2(pack_bf2(v.x-hx, v.y-hy), pack_bf2(v.z-hz, v.w-hw));
}

// ------- fused weight: pure HMMA GEMM (measured 56us) -------
#define MT_KC    64
#define MT_AH    0
#define MT_AL    8192
#define MT_BH    16384
#define MT_BL    32768
#define MT_ST    49152
#define MT_SMEM  (3*MT_ST)

__device__ __forceinline__ void mt_load_stage(uint32_t sbase, int j0, int k0, int pt, int tid) {
#pragma unroll
    for (int h = 0; h < 2; h++) {
        int u = tid + h*256; int r = u >> 3, c = u & 7;
        uint32_t so = sbase + MT_AH + SW128(r*128 + c*16);
        cp_async16(so, (const char*)g_wihh + ((size_t)(j0+r)*PROJ + pt)*2 + c*16);
    }
#pragma unroll
    for (int h = 0; h < 2; h++) {
        int u = tid + h*256; int r = u >> 3, c = u & 7;
        uint32_t so = sbase + MT_AL + SW128(r*128 + c*16);
        cp_async16(so, (const char*)g_wihl + ((size_t)(j0+r)*PROJ + pt)*2 + c*16);
    }
#pragma unroll
    for (int h = 0; h < 4; h++) {
        int u = tid + h*256; int r = u >> 3, c = u & 7;
        uint32_t so = sbase + MT_BH + SW128(r*128 + c*16);
        cp_async16(so, (const char*)g_pwh + ((size_t)(k0+r)*PROJ + pt)*2 + c*16);
    }
#pragma unroll
    for (int h = 0; h < 4; h++) {
        int u = tid + h*256; int r = u >> 3, c = u & 7;
        uint32_t so = sbase + MT_BL + SW128(r*128 + c*16);
        cp_async16(so, (const char*)g_pwl + ((size_t)(k0+r)*PROJ + pt)*2 + c*16);
    }
}

__global__ void __launch_bounds__(256, 1) k_mt_mma() {
    extern __shared__ __align__(1024) char smem[];
    const uint32_t smem_u = smem_to_u32(smem);
    const int tid = threadIdx.x, wid = tid >> 5, lane = tid & 31;
    const int k0 = blockIdx.x * 128;
    const int j0 = blockIdx.y * 64;

    const int wm = (wid >> 2) * 32;
    const int wn = (wid & 3) * 32;
    const int a_m  = (lane & 15);
    const int a_kh = (lane >> 4) * 16;
    const int b_n  = (lane & 7) + ((lane >> 4) & 1) * 8;
    const int b_kh = ((lane >> 3) & 1) * 16;

    float acc[2][4][4];
#pragma unroll
    for (int mt = 0; mt < 2; mt++)
#pragma unroll
        for (int nt = 0; nt < 4; nt++)
#pragma unroll
            for (int q = 0; q < 4; q++) acc[mt][nt][q] = 0.f;

    mt_load_stage(smem_u,           j0, k0, 0,       tid); cp_commit();
    mt_load_stage(smem_u + MT_ST,   j0, k0, MT_KC,   tid); cp_commit();
    mt_load_stage(smem_u + 2*MT_ST, j0, k0, 2*MT_KC, tid); cp_commit();

    const int NCH = PROJ / MT_KC;
    int buf = 0;
    for (int i = 0; i < NCH; i++) {
        cp_wait<2>();
        __syncthreads();
        const uint32_t sb = smem_u + buf * MT_ST;
#pragma unroll
        for (int kk = 0; kk < 4; kk++) {
            const int kb = kk * 32;
            uint32_t ah[2][4], al[2][4];
#pragma unroll
            for (int mt = 0; mt < 2; mt++) {
                int m = wm + mt*16 + a_m;
                uint32_t off = SW128(m*128 + kb + a_kh);
                ldsm_x4(ah[mt], sb + MT_AH + off);
                ldsm_x4(al[mt], sb + MT_AL + off);
            }
            uint32_t bh[2][4], bl[2][4];
#pragma unroll
            for (int p = 0; p < 2; p++) {
                int n = wn + p*16 + b_n;
                uint32_t off = SW128(n*128 + kb + b_kh);
                ldsm_x4(bh[p], sb + MT_BH + off);
                ldsm_x4(bl[p], sb + MT_BL + off);
            }
#pragma unroll
            for (int mt = 0; mt < 2; mt++)
#pragma unroll
                for (int nt = 0; nt < 4; nt++) {
                    const uint32_t* pbh = &bh[nt >> 1][(nt & 1) * 2];
                    const uint32_t* pbl = &bl[nt >> 1][(nt & 1) * 2];
                    mma16816(acc[mt][nt], ah[mt], pbh);
                    mma16816(acc[mt][nt], ah[mt], pbl);
                    mma16816(acc[mt][nt], al[mt], pbh);
                }
        }
        __syncthreads();
        if (i + 3 < NCH) mt_load_stage(smem_u + buf * MT_ST, j0, k0, (i + 3) * MT_KC, tid);
        cp_commit();
        buf = (buf + 1 == 3) ? 0 : buf + 1;
    }

    const int em = (lane >> 2);
    const int en = (lane & 3) * 2;
#pragma unroll
    for (int mt = 0; mt < 2; mt++)
#pragma unroll
        for (int nt = 0; nt < 4; nt++) {
            int col = k0 + wn + nt*8 + en;
#pragma unroll
            for (int half = 0; half < 2; half++) {
                int m = j0 + wm + mt*16 + em + half*8;
                float a0 = acc[mt][nt][half*2 + 0];
                float a1 = acc[mt][nt][half*2 + 1];
                float h0 = __bfloat162float(__float2bfloat16(a0));
                float h1 = __bfloat162float(__float2bfloat16(a1));
                *(uint32_t*)(g_Bhi + (size_t)m*FLAT + col) = pack_bf2(h0, h1);
                *(uint32_t*)(g_Blo + (size_t)m*FLAT + col) = pack_bf2(a0-h0, a1-h1);
            }
        }
}

// ---------------- small inits / graph preprocessing ----------------
__global__ void k_init_graph() {
    int n = blockIdx.x*256 + threadIdx.x;
    if (n < NN) { g_deg[n] = 1.0f; g_cnt[n] = 1; }
}

__global__ void k_init_state() {
    int i = blockIdx.x*256 + threadIdx.x;
    if (i < NN*HID) {
        g_h[i] = 0.f; g_c[i] = 0.f;
        g_hh[i] = __float2bfloat16(0.f);
        g_hl[i] = __float2bfloat16(0.f);
    }
}

__global__ void k_edge(const int* __restrict__ ei, const float* __restrict__ ea) {
    int e = blockIdx.x*256 + threadIdx.x;
    if (e < EE) {
        int d = ei[EE + e];
        atomicAdd(&g_deg[d], ea[e]);
        atomicAdd(&g_cnt[d], 1);
    }
}

__global__ void k_scan() {
    __shared__ int sums[1024];
    int t = threadIdx.x;
    int loc[8]; int s = 0;
#pragma unroll
    for (int i = 0; i < 8; i++) { loc[i] = s; s += g_cnt[t*8 + i]; }
    sums[t] = s;
    __syncthreads();
    for (int off = 1; off < 1024; off <<= 1) {
        int v = sums[t];
        int add = (t >= off) ? sums[t - off] : 0;
        __syncthreads();
        sums[t] = v + add;
        __syncthreads();
    }
    int base = (t > 0) ? sums[t-1] : 0;
#pragma unroll
    for (int i = 0; i < 8; i++) {
        int rp = base + loc[i];
        g_rowptr[t*8 + i] = rp;
        g_cursor[t*8 + i] = rp;
    }
    if (t == 1023) g_rowptr[NN] = sums[1023];
#pragma unroll
    for (int i = 0; i < 8; i++) {
        float d = g_deg[t*8 + i];
        g_dinv[t*8 + i] = (d > 0.f) ? rsqrtf(d) : 0.f;
    }
}

__global__ void k_scatter(const int* __restrict__ ei, const float* __restrict__ ea) {
    int e = blockIdx.x*256 + threadIdx.x;
    if (e < TE) {
        int s, d; float w;
        if (e < EE) { s = ei[e]; d = ei[EE + e]; w = ea[e]; }
        else        { s = d = e - EE; w = 1.0f; }
        int pos = atomicAdd(&g_cursor[d], 1);
        g_esrc[pos]  = s;
        g_enorm[pos] = g_dinv[s] * w * g_dinv[d];
    }
}

// ---------------- GCN ----------------
__global__ void k_spmm(const float* __restrict__ xin, int sel, int L4) {
    const float4* x = (sel == 0) ? (const float4*)xin
                     : (sel == 1) ? (const float4*)g_xA : (const float4*)g_xB;
    int gid = blockIdx.x*256 + threadIdx.x;
    if (gid >= NN * L4) return;
    int n = gid / L4;
    int v = gid - n*L4;
    int e0 = g_rowptr[n], e1 = g_rowptr[n+1];
    float ax = 0.f, ay = 0.f, az = 0.f, aw = 0.f;
    for (int e = e0; e < e1; e++) {
        float w = g_enorm[e];
        int   s = g_esrc[e];
        float4 xv = x[(size_t)s*L4 + v];
        ax += w*xv.x; ay += w*xv.y; az += w*xv.z; aw += w*xv.w;
    }
    ((float4*)g_agg)[gid] = make_float4(ax, ay, az, aw);
}

template<int FI, int FO, int SELO>
__global__ void __launch_bounds__(256) k_gcn(const float* __restrict__ W, const float* __restrict__ b) {
    float* xo = (SELO == 1) ? g_xA : g_xB;
    __shared__ float Ws[FI*FO];
    __shared__ float As[32*FI];
    __shared__ float bs[FO];
    int tid = threadIdx.x;
    int r0 = blockIdx.x * 32;
    for (int i = tid; i < FI*FO; i += 256) { int o = i / FI, c = i - o*FI; Ws[c*FO + o] = W[i]; }
    for (int i = tid; i < FO; i += 256) bs[i] = b[i];
    for (int i = tid; i < 32*FI; i += 256) As[i] = g_agg[(size_t)r0*FI + i];
    __syncthreads();
    const int CG = FO / 2;
    for (int u = tid; u < 8*CG; u += 256) {
        int rg = u / CG; int cg = u - rg*CG;
        int r = rg*4, o = cg*2;
        float a00=0,a01=0,a10=0,a11=0,a20=0,a21=0,a30=0,a31=0;
#pragma unroll
        for (int c = 0; c < FI; c++) {
            float w0 = Ws[c*FO + o], w1 = Ws[c*FO + o + 1];
            float x0 = As[(r+0)*FI + c], x1 = As[(r+1)*FI + c];
            float x2 = As[(r+2)*FI + c], x3 = As[(r+3)*FI + c];
            a00 += x0*w0; a01 += x0*w1;
            a10 += x1*w0; a11 += x1*w1;
            a20 += x2*w0; a21 += x2*w1;
            a30 += x3*w0; a31 += x3*w1;
        }
        float* p0 = xo + (size_t)(r0+r  )*FO;
        float* p1 = xo + (size_t)(r0+r+1)*FO;
        float* p2 = xo + (size_t)(r0+r+2)*FO;
        float* p3 = xo + (size_t)(r0+r+3)*FO;
        p0[o] = tanhf(a00 + bs[o]); p0[o+1] = tanhf(a01 + bs[o+1]);
        p1[o] = tanhf(a10 + bs[o]); p1[o+1] = tanhf(a11 + bs[o+1]);
        p2[o] = tanhf(a20 + bs[o]); p2[o+1] = tanhf(a21 + bs[o+1]);
        p3[o] = tanhf(a30 + bs[o]); p3[o+1] = tanhf(a31 + bs[o+1]);
    }
}

// HMMA transform for big layers (FI 32/64)
template<int FI, int FO, int SELO>
__global__ void __launch_bounds__(256) k_gcn_mma(const float* __restrict__ W, const float* __restrict__ b) {
    float* xo = (SELO == 1) ? g_xA : g_xB;
    extern __shared__ __align__(1024) char smem[];
    const int SA = 128*128;
    const int SB = FO*128;
    const uint32_t uAH = smem_to_u32(smem);
    const uint32_t uAL = uAH + SA;
    const uint32_t uBH = uAH + 2*SA;
    const uint32_t uBL = uAH + 2*SA + SB;
    float* pb = (float*)(smem + 2*SA + 2*SB);
    const int tid = threadIdx.x, wid = tid >> 5, lane = tid & 31;
    const int r0 = blockIdx.x * 128;

    for (int idx = tid; idx < 128*FI/4; idx += 256) {
        int r  = idx / (FI/4);
        int c4 = idx % (FI/4);
        float4 v = *(const float4*)(g_agg + (size_t)(r0+r)*FI + c4*4);
        uint32_t sw = (uint32_t)(r*128 + c4*8) ^ ((uint32_t)(r & 7) << 4);
        float hx = __bfloat162float(__float2bfloat16(v.x));
        float hy = __bfloat162float(__float2bfloat16(v.y));
        float hz = __bfloat162float(__float2bfloat16(v.z));
        float hw = __bfloat162float(__float2bfloat16(v.w));
        *(uint32_t*)((char*)smem + sw)            = pack_bf2(hx, hy);
        *(uint32_t*)((char*)smem + sw + 4)        = pack_bf2(hz, hw);
        *(uint32_t*)((char*)smem + SA + sw)       = pack_bf2(v.x - hx, v.y - hy);
        *(uint32_t*)((char*)smem + SA + sw + 4)   = pack_bf2(v.z - hz, v.w - hw);
    }
    for (int idx = tid; idx < FO*FI/4; idx += 256) {
        int r  = idx / (FI/4);
        int c4 = idx % (FI/4);
        float4 v = *(const float4*)(W + (size_t)r*FI + c4*4);
        uint32_t sw = (uint32_t)(r*128 + c4*8) ^ ((uint32_t)(r & 7) << 4);
        float hx = __bfloat162float(__float2bfloat16(v.x));
        float hy = __bfloat162float(__float2bfloat16(v.y));
        float hz = __bfloat162float(__float2bfloat16(v.z));
        float hw = __bfloat162float(__float2bfloat16(v.w));
        *(uint32_t*)((char*)smem + 2*SA + sw)          = pack_bf2(hx, hy);
        *(uint32_t*)((char*)smem + 2*SA + sw + 4)      = pack_bf2(hz, hw);
        *(uint32_t*)((char*)smem + 2*SA + SB + sw)     = pack_bf2(v.x - hx, v.y - hy);
        *(uint32_t*)((char*)smem + 2*SA + SB + sw + 4) = pack_bf2(v.z - hz, v.w - hw);
    }
    for (int i = tid; i < FO; i += 256) pb[i] = b[i];
    __syncthreads();

    constexpr int NT  = (FO == 128) ? 8 : 4;
    constexpr int NPT = NT / 2;
    const int wm = (wid >> 1) * 32;
    const int wn = (wid & 1) * (FO / 2);
    const int a_m  = (lane & 15);
    const int a_kh = (lane >> 4) * 16;
    const int b_n  = (lane & 7) + ((lane >> 4) & 1) * 8;
    const int b_kh = ((lane >> 3) & 1) * 16;

    float acc[2][NT][4];
#pragma unroll
    for (int mt = 0; mt < 2; mt++)
#pragma unroll
        for (int nt = 0; nt < NT; nt++)
#pragma unroll
            for (int q = 0; q < 4; q++) acc[mt][nt][q] = 0.f;

#pragma unroll
    for (int kk = 0; kk < FI/16; kk++) {
        const int kb = kk * 32;
        uint32_t ah[2][4], al[2][4];
#pragma unroll
        for (int mt = 0; mt < 2; mt++) {
            int m = wm + mt*16 + a_m;
            uint32_t off = (uint32_t)(m*128 + kb + a_kh) ^ ((uint32_t)(m & 7) << 4);
            ldsm_x4(ah[mt], uAH + off);
            ldsm_x4(al[mt], uAL + off);
        }
        uint32_t bh[NPT][4], bl[NPT][4];
#pragma unroll
        for (int p = 0; p < NPT; p++) {
            int n = wn + p*16 + b_n;
            uint32_t off = (uint32_t)(n*128 + kb + b_kh) ^ ((uint32_t)(n & 7) << 4);
            ldsm_x4(bh[p], uBH + off);
            ldsm_x4(bl[p], uBL + off);
        }
#pragma unroll
        for (int mt = 0; mt < 2; mt++)
#pragma unroll
            for (int nt = 0; nt < NT; nt++) {
                const uint32_t* pbh = &bh[nt >> 1][(nt & 1) * 2];
                const uint32_t* pbl = &bl[nt >> 1][(nt & 1) * 2];
                mma16816(acc[mt][nt], ah[mt], pbh);
                mma16816(acc[mt][nt], ah[mt], pbl);
                mma16816(acc[mt][nt], al[mt], pbh);
            }
    }

    const int em = (lane >> 2);
    const int en = (lane & 3) * 2;
#pragma unroll
    for (int mt = 0; mt < 2; mt++)
#pragma unroll
        for (int nt = 0; nt < NT; nt++) {
            int col = wn + nt*8 + en;
            int m   = r0 + wm + mt*16 + em;
            float b0 = pb[col], b1 = pb[col+1];
            float2 v0 = make_float2(tanhf(acc[mt][nt][0] + b0), tanhf(acc[mt][nt][1] + b1));
            float2 v1 = make_float2(tanhf(acc[mt][nt][2] + b0), tanhf(acc[mt][nt][3] + b1));
            *(float2*)(xo + (size_t)m * FO + col)       = v0;
            *(float2*)(xo + (size_t)(m + 8) * FO + col) = v1;
        }
}

// ------- conv+pool: per-node scalar -------
__global__ void k_convpool(const float* __restrict__ cw, const float* __restrict__ cb) {
    __shared__ __align__(16) float xs[SS*YC];
    __shared__ float cws[10], cbs[2];
    int n = blockIdx.x;
    int tid = threadIdx.x;
    const float4* src = (const float4*)(g_xA + (size_t)n*SS*YC);
    for (int i = tid; i < SS*YC/4; i += 256) ((float4*)xs)[i] = src[i];
    if (tid < 10) cws[tid] = cw[tid];
    if (tid < 2)  cbs[tid] = cb[tid];
    __syncthreads();
#pragma unroll
    for (int w = 0; w < NWIN; w++) {
        const float* win = xs + w*YC;
        size_t obase = (size_t)(n*NWIN + w)*FLAT;
        for (int i = tid; i < FLAT; i += 256) {
            int f = i / 1280;
            int q = i - f*1280;
            int p0 = q*2;
            float v0 = cbs[f], v1 = cbs[f];
#pragma unroll
            for (int k = 0; k < 5; k++) {
                int p = p0 + k - 2;
                if (p >= 0 && p < FLAT) v0 += win[p] * cws[f*5 + k];
                p += 1;
                if (p >= 0 && p < FLAT) v1 += win[p] * cws[f*5 + k];
            }
            float v = fmaxf(v0, v1);
            __nv_bfloat16 h = __float2bfloat16(v);
            float lo = v - __bfloat162float(h);
            g_Ahi[obase + i] = h;
            g_Alo[obase + i] = __float2bfloat16(lo);
        }
    }
}

// ------- fused bias: one warp per output j -------
__global__ void __launch_bounds__(256) k_fb(const float* __restrict__ wih, const float* __restrict__ pb,
                     const float* __restrict__ bih, const float* __restrict__ bhh) {
    int wix = (blockIdx.x*256 + threadIdx.x) >> 5;
    int lane = threadIdx.x & 31;
    if (wix >= GATE) return;
    const float* row = wih + (size_t)wix*PROJ;
    float acc = 0.f;
#pragma unroll 8
    for (int p = lane; p < PROJ; p += 32) acc += row[p] * pb[p];
#pragma unroll
    for (int o = 16; o > 0; o >>= 1) acc += __shfl_xor_sync(0xFFFFFFFFu, acc, o);
    if (lane == 0) g_fb[wix] = acc + bih[wix] + bhh[wix];
}

// ============ gates GEMM: KC=64, 3-stage (round-11 config, 1372us run) ============
#define GK_KC    64
#define GK_NCH   (FLAT/GK_KC)
#define ST_AH    0
#define ST_AL    16384
#define ST_BH    32768
#define ST_BL    49152
#define ST_SIZE  65536
#define GK_SMEM  (3*ST_SIZE + 512)

__device__ __forceinline__ void gk_load_stage(uint32_t sbase, int m0, int j0, int kt, int tid) {
    const char* gbase[4] = {
        (const char*)g_Ahi, (const char*)g_Alo, (const char*)g_Bhi, (const char*)g_Blo };
    const int row0[4] = { m0, m0, j0, j0 };
#pragma unroll
    for (int h = 0; h < 16; h++) {
        int tile = h >> 2;
        int v    = tid + (h & 3) * 256;
        int r    = v >> 3;
        int c    = v & 7;
        uint32_t so = sbase + tile*16384 + SW128(r*128 + c*16);
        const char* gp = gbase[tile] + ((size_t)(row0[tile] + r) * FLAT + kt) * 2 + c*16;
        cp_async16(so, gp);
    }
}

__global__ void __launch_bounds__(256, 1) k_gates_hmma() {
    extern __shared__ __align__(1024) char smem[];
    const uint32_t smem_u = smem_to_u32(smem);
    float* fbs = (float*)(smem + 3*ST_SIZE);
    const int tid = threadIdx.x;
    const int wid = tid >> 5;
    const int lane = tid & 31;
    const int j0 = blockIdx.x * 128;
    const int m0 = blockIdx.y * 128;
    const int wm = (wid >> 1) * 32;
    const int wn = (wid & 1) * 64;

    if (tid < 128) fbs[tid] = g_fb[j0 + tid];

    float acc[2][8][4];
#pragma unroll
    for (int mt = 0; mt < 2; mt++)
#pragma unroll
        for (int nt = 0; nt < 8; nt++)
#pragma unroll
            for (int q = 0; q < 4; q++) acc[mt][nt][q] = 0.f;

    gk_load_stage(smem_u,             m0, j0, 0,        tid); cp_commit();
    gk_load_stage(smem_u + ST_SIZE,   m0, j0, GK_KC,    tid); cp_commit();
    gk_load_stage(smem_u + 2*ST_SIZE, m0, j0, 2*GK_KC,  tid); cp_commit();

    const int a_m  = (lane & 15);
    const int a_kh = (lane >> 4) * 16;
    const int b_n  = (lane & 7) + ((lane >> 4) & 1) * 8;
    const int b_kh = ((lane >> 3) & 1) * 16;

    int buf = 0;
    for (int i = 0; i < GK_NCH; i++) {
        cp_wait<2>();
        __syncthreads();
        const uint32_t sb = smem_u + buf * ST_SIZE;

#pragma unroll
        for (int kk = 0; kk < 4; kk++) {
            const int kb = kk * 32;
            uint32_t ah[2][4], al[2][4];
#pragma unroll
            for (int mt = 0; mt < 2; mt++) {
                int m = wm + mt*16 + a_m;
                uint32_t off = SW128(m*128 + kb + a_kh);
                ldsm_x4(ah[mt], sb + ST_AH + off);
                ldsm_x4(al[mt], sb + ST_AL + off);
            }
            uint32_t bh[4][4], bl[4][4];
#pragma unroll
            for (int p = 0; p < 4; p++) {
                int n = wn + p*16 + b_n;
                uint32_t off = SW128(n*128 + kb + b_kh);
                ldsm_x4(bh[p], sb + ST_BH + off);
                ldsm_x4(bl[p], sb + ST_BL + off);
            }
#pragma unroll
            for (int mt = 0; mt < 2; mt++)
#pragma unroll
                for (int nt = 0; nt < 8; nt++) {
                    const uint32_t* pbh = &bh[nt >> 1][(nt & 1) * 2];
                    const uint32_t* pbl = &bl[nt >> 1][(nt & 1) * 2];
                    mma16816(acc[mt][nt], ah[mt], pbh);
                    mma16816(acc[mt][nt], ah[mt], pbl);
                    mma16816(acc[mt][nt], al[mt], pbh);
                }
        }
        __syncthreads();
        if (i + 3 < GK_NCH) {
            gk_load_stage(smem_u + buf * ST_SIZE, m0, j0, (i + 3) * GK_KC, tid);
        }
        cp_commit();
        buf = (buf + 1 == 3) ? 0 : buf + 1;
    }

    const int em = (lane >> 2);
    const int en = (lane & 3) * 2;
#pragma unroll
    for (int mt = 0; mt < 2; mt++) {
#pragma unroll
        for (int nt = 0; nt < 8; nt++) {
            int nl = wn + nt*8 + en;
            int m  = m0 + wm + mt*16 + em;
            float f0 = fbs[nl], f1 = fbs[nl + 1];
            float2 v0 = make_float2(acc[mt][nt][0] + f0, acc[mt][nt][1] + f1);
            float2 v1 = make_float2(acc[mt][nt][2] + f0, acc[mt][nt][3] + f1);
            *(float2*)(g_gates + (size_t)m * GATE + j0 + nl)       = v0;
            *(float2*)(g_gates + (size_t)(m + 8) * GATE + j0 + nl) = v1;
        }
    }
}

// ---------------- LSTM: HMMA recurrent gemm ----------------
#define LG_SMEM (2*16384 + 2*32768)
__global__ void __launch_bounds__(256) k_lstm_mma(int t) {
    extern __shared__ __align__(1024) char smem[];
    const uint32_t uAH = smem_to_u32(smem);
    const uint32_t uAL = uAH + 16384;
    const uint32_t uBH = uAH + 32768;
    const uint32_t uBL = uAH + 65536;
    const int tid = threadIdx.x, wid = tid >> 5, lane = tid & 31;
    const int j0 = blockIdx.x * 128;
    const int n0 = blockIdx.y * 64;

    for (int u = tid; u < 1024; u += 256) {
        int r = u >> 4, c8 = u & 15;
        int row = r + 64*(c8 >> 3);
        uint32_t sw = (uint32_t)(row*128 + (c8 & 7)*16) ^ ((uint32_t)(row & 7) << 4);
        *(uint4*)((char*)smem + sw)         = *(const uint4*)(g_hh + (size_t)(n0+r)*HID + c8*8);
        *(uint4*)((char*)smem + 16384 + sw) = *(const uint4*)(g_hl + (size_t)(n0+r)*HID + c8*8);
    }
    for (int u = tid; u < 2048; u += 256) {
        int r = u >> 4, c8 = u & 15;
        int row = r + 128*(c8 >> 3);
        uint32_t sw = (uint32_t)(row*128 + (c8 & 7)*16) ^ ((uint32_t)(row & 7) << 4);
        *(uint4*)((char*)smem + 32768 + sw) = *(const uint4*)(g_whhh + (size_t)(j0+r)*HID + c8*8);
        *(uint4*)((char*)smem + 65536 + sw) = *(const uint4*)(g_whhl + (size_t)(j0+r)*HID + c8*8);
    }
    __syncthreads();

    const int wm = (wid >> 2) * 32;
    const int wn = (wid & 3) * 32;
    const int a_m  = (lane & 15);
    const int a_kh = (lane >> 4) * 16;
    const int b_n  = (lane & 7) + ((lane >> 4) & 1) * 8;
    const int b_kh = ((lane >> 3) & 1) * 16;

    float acc[2][4][4];
#pragma unroll
    for (int mt = 0; mt < 2; mt++)
#pragma unroll
        for (int nt = 0; nt < 4; nt++)
#pragma unroll
            for (int q = 0; q < 4; q++) acc[mt][nt][q] = 0.f;

#pragma unroll
    for (int kk = 0; kk < 8; kk++) {
        const int half = kk >> 2;
        const int kb = (kk & 3) * 32;
        uint32_t ah[2][4], al[2][4];
#pragma unroll
        for (int mt = 0; mt < 2; mt++) {
            int m = wm + mt*16 + a_m;
            int row = m + 64*half;
            uint32_t off = (uint32_t)(row*128 + kb + a_kh) ^ ((uint32_t)(row & 7) << 4);
            ldsm_x4(ah[mt], uAH + off);
            ldsm_x4(al[mt], uAL + off);
        }
        uint32_t bh[2][4], bl[2][4];
#pragma unroll
        for (int p = 0; p < 2; p++) {
            int nj = wn + p*16 + b_n;
            int row = nj + 128*half;
            uint32_t off = (uint32_t)(row*128 + kb + b_kh) ^ ((uint32_t)(row & 7) << 4);
            ldsm_x4(bh[p], uBH + off);
            ldsm_x4(bl[p], uBL + off);
        }
#pragma unroll
        for (int mt = 0; mt < 2; mt++)
#pragma unroll
            for (int nt = 0; nt < 4; nt++) {
                const uint32_t* pbh = &bh[nt >> 1][(nt & 1) * 2];
                const uint32_t* pbl = &bl[nt >> 1][(nt & 1) * 2];
                mma16816(acc[mt][nt], ah[mt], pbh);
                mma16816(acc[mt][nt], ah[mt], pbl);
                mma16816(acc[mt][nt], al[mt], pbh);
            }
    }

    const int em = (lane >> 2);
    const int en = (lane & 3) * 2;
#pragma unroll
    for (int mt = 0; mt < 2; mt++)
#pragma unroll
        for (int nt = 0; nt < 4; nt++) {
            int jj = j0 + wn + nt*8 + en;
#pragma unroll
            for (int half = 0; half < 2; half++) {
                int n = n0 + wm + mt*16 + em + half*8;
                float2 gx = *(const float2*)(g_gates + ((size_t)n*4 + t)*GATE + jj);
                float2 v = make_float2(acc[mt][nt][half*2+0] + gx.x,
                                       acc[mt][nt][half*2+1] + gx.y);
                *(float2*)(g_gbuf + (size_t)n*GATE + jj) = v;
            }
        }
}

__device__ __forceinline__ float sigf(float x) { return 1.0f / (1.0f + expf(-x)); }

__global__ void k_lstm_point() {
    int idx = blockIdx.x*256 + threadIdx.x;
    if (idx < NN*HID) {
        int n = idx >> 7, j = idx & 127;
        const float* g = g_gbuf + (size_t)n*GATE;
        float gi = g[j], gf = g[HID + j], gg = g[2*HID + j], go = g[3*HID + j];
        float c = sigf(gf) * g_c[idx] + sigf(gi) * tanhf(gg);
        g_c[idx] = c;
        float h = sigf(go) * tanhf(c);
        g_h[idx] = h;
        __nv_bfloat16 hb = __float2bfloat16(h);
        g_hh[idx] = hb;
        g_hl[idx] = __float2bfloat16(h - __bfloat162float(hb));
    }
}

// ---------------- output head ----------------
__global__ void k_out(const float* __restrict__ ow, const float* __restrict__ ob,
                      float* __restrict__ out) {
    int idx = blockIdx.x*256 + threadIdx.x;
    if (idx < NN*LBL) {
        int n = idx / LBL, l = idx - n*LBL;
        float acc = ob[l];
        const float* hr = g_h + (size_t)n*HID;
        const float* wr = ow + (size_t)l*HID;
#pragma unroll 8
        for (int k = 0; k < HID; k++) acc += hr[k]*wr[k];
        out[idx] = acc;
    }
}

// ---------------- launch ----------------
extern "C" void kernel_launch(void* const* d_in, const int* in_sizes, int n_in,
                              void* d_out, int out_size) {
    const float* inputs = (const float*)d_in[0];
    const int*   ei     = (const int*)  d_in[1];
    const float* ea     = (const float*)d_in[2];
    const float* W1 = (const float*)d_in[3];  const float* b1 = (const float*)d_in[4];
    const float* W2 = (const float*)d_in[5];  const float* b2 = (const float*)d_in[6];
    const float* W3 = (const float*)d_in[7];  const float* b3 = (const float*)d_in[8];
    const float* W4 = (const float*)d_in[9];  const float* b4 = (const float*)d_in[10];
    const float* W5 = (const float*)d_in[11]; const float* b5 = (const float*)d_in[12];
    const float* cw  = (const float*)d_in[13]; const float* cb  = (const float*)d_in[14];
    const float* pw  = (const float*)d_in[15]; const float* pb  = (const float*)d_in[16];
    const float* wih = (const float*)d_in[17]; const float* whh = (const float*)d_in[18];
    const float* bih = (const float*)d_in[19]; const float* bhh = (const float*)d_in[20];
    const float* ow  = (const float*)d_in[21]; const float* ob  = (const float*)d_in[22];
    float* out = (float*)d_out;

    const int SMEM_GCN4 = 2*16384 + 2*64*128  + 256;
    const int SMEM_GCN5 = 2*16384 + 2*128*128 + 512;
    cudaFuncSetAttribute(k_gates_hmma, cudaFuncAttributeMaxDynamicSharedMemorySize, GK_SMEM);
    cudaFuncSetAttribute(k_gcn_mma<32,64,2>,  cudaFuncAttributeMaxDynamicSharedMemorySize, SMEM_GCN4);
    cudaFuncSetAttribute(k_gcn_mma<64,128,1>, cudaFuncAttributeMaxDynamicSharedMemorySize, SMEM_GCN5);
    cudaFuncSetAttribute(k_mt_mma,  cudaFuncAttributeMaxDynamicSharedMemorySize, MT_SMEM);
    cudaFuncSetAttribute(k_lstm_mma, cudaFuncAttributeMaxDynamicSharedMemorySize, LG_SMEM);

    // side stream for the independent weight-prep chain (created once; events are
    // recorded/waited every call so the captured graph is identical each time)
    static cudaStream_t s2 = nullptr;
    static cudaEvent_t evF = nullptr, evJ = nullptr;
    if (s2 == nullptr) {
        cudaStreamCreateWithFlags(&s2, cudaStreamNonBlocking);
        cudaEventCreateWithFlags(&evF, cudaEventDisableTiming);
        cudaEventCreateWithFlags(&evJ, cudaEventDisableTiming);
    }

    // fork: weight-prep chain on s2 (depends only on kernel inputs)
    cudaEventRecord(evF, 0);
    cudaStreamWaitEvent(s2, evF, 0);
    k_pw_split<<<dim3(FLAT/64, PROJ/32), 256, 0, s2>>>(pw);
    k_wih_split<<<GATE*PROJ/4/256, 256, 0, s2>>>(wih);
    k_whh_split<<<GATE*HID/4/256, 256, 0, s2>>>(whh);
    k_mt_mma<<<dim3(FLAT/128, GATE/64), 256, MT_SMEM, s2>>>();
    k_fb<<<GATE/8, 256, 0, s2>>>(wih, pb, bih, bhh);
    cudaEventRecord(evJ, s2);

    // main chain: graph preprocessing + GCN + convpool
    k_init_graph<<<32, 256>>>();
    k_init_state<<<4096, 256>>>();
    k_edge<<<EE/256, 256>>>(ei, ea);
    k_scan<<<1, 1024>>>();
    k_scatter<<<(TE + 255)/256, 256>>>(ei, ea);

    k_spmm<<<(NN*24  + 255)/256, 256>>>(inputs, 0, 24);
    k_gcn<4, 8, 1><<<6144, 256>>>(W1, b1);
    k_spmm<<<(NN*48  + 255)/256, 256>>>(nullptr, 1, 48);
    k_gcn<8, 16, 2><<<6144, 256>>>(W2, b2);
    k_spmm<<<(NN*96  + 255)/256, 256>>>(nullptr, 2, 96);
    k_gcn<16, 32, 1><<<6144, 256>>>(W3, b3);
    k_spmm<<<(NN*192 + 255)/256, 256>>>(nullptr, 1, 192);
    k_gcn_mma<32, 64, 2><<<1536, 256, SMEM_GCN4>>>(W4, b4);
    k_spmm<<<(NN*384 + 255)/256, 256>>>(nullptr, 2, 384);
    k_gcn_mma<64, 128, 1><<<1536, 256, SMEM_GCN5>>>(W5, b5);

    k_convpool<<<NN, 256>>>(cw, cb);

    // join: gates needs g_Bhi/g_Blo/g_fb (s2) and g_Ahi/g_Alo (main)
    cudaStreamWaitEvent(0, evJ, 0);

    k_gates_hmma<<<dim3(4, 256), 256, GK_SMEM>>>();

    for (int t = 0; t < NWIN; t++) {
        k_lstm_mma<<<dim3(4, 128), 256, LG_SMEM>>>(t);
        k_lstm_point<<<4096, 256>>>();
    }

    k_out<<<(NN*LBL + 255)/256, 256>>>(ow, ob, out);
}

// round 16
// speedup vs baseline: 1.2355x; 1.1065x over previous
#include <cuda_runtime.h>
#include <cuda_bf16.h>
#include <math.h>
#include <stdint.h>

#define NN    8192
#define SS    24
#define CC    4
#define EE    65536
#define TE    (EE+NN)
#define WINL  20
#define NWIN  4
#define YC    128
#define FLAT  2560
#define PROJ  1280
#define HID   128
#define GATE  512
#define NB    (NN*NWIN)
#define LBL   12

// ================= PTX helpers (sm_100 base ISA only) =================
__device__ __forceinline__ uint32_t smem_to_u32(const void* p) {
    uint32_t a;
    asm("{ .reg .u64 t; cvta.to.shared.u64 t, %1; cvt.u32.u64 %0, t; }" : "=r"(a) : "l"(p));
    return a;
}
__device__ __forceinline__ void cp_async16(uint32_t s, const void* g) {
    asm volatile("cp.async.cg.shared.global [%0], [%1], 16;" :: "r"(s), "l"(g));
}
__device__ __forceinline__ void cp_commit() { asm volatile("cp.async.commit_group;" ::: "memory"); }
template<int W> __device__ __forceinline__ void cp_wait() {
    asm volatile("cp.async.wait_group %0;" :: "n"(W) : "memory");
}
__device__ __forceinline__ void ldsm_x4(uint32_t* r, uint32_t a) {
    asm volatile("ldmatrix.sync.aligned.m8n8.x4.shared.b16 {%0,%1,%2,%3}, [%4];"
        : "=r"(r[0]), "=r"(r[1]), "=r"(r[2]), "=r"(r[3]) : "r"(a));
}
__device__ __forceinline__ void mma16816(float* c, const uint32_t* a, const uint32_t* b) {
    asm volatile("mma.sync.aligned.m16n8k16.row.col.f32.bf16.bf16.f32 "
        "{%0,%1,%2,%3}, {%4,%5,%6,%7}, {%8,%9}, {%0,%1,%2,%3};"
        : "+f"(c[0]), "+f"(c[1]), "+f"(c[2]), "+f"(c[3])
        : "r"(a[0]), "r"(a[1]), "r"(a[2]), "r"(a[3]), "r"(b[0]), "r"(b[1]));
}
__device__ __forceinline__ void mma16808_tf32(float* c, const uint32_t* a, uint32_t b0, uint32_t b1) {
    asm volatile("mma.sync.aligned.m16n8k8.row.col.f32.tf32.tf32.f32 "
        "{%0,%1,%2,%3}, {%4,%5,%6,%7}, {%8,%9}, {%0,%1,%2,%3};"
        : "+f"(c[0]), "+f"(c[1]), "+f"(c[2]), "+f"(c[3])
        : "r"(a[0]), "r"(a[1]), "r"(a[2]), "r"(a[3]), "r"(b0), "r"(b1));
}
__device__ __forceinline__ uint32_t f2tf32(float v) {
    uint32_t u;
    asm("cvt.rna.tf32.f32 %0, %1;" : "=r"(u) : "f"(v));
    return u;
}
#define SW128(off) ((off) ^ (((off) >> 3) & 0x70))
__device__ __forceinline__ uint32_t pack_bf2(float a, float b) {
    __nv_bfloat162 v = __floats2bfloat162_rn(a, b);
    return *(uint32_t*)&v;
}

// ---------------- scratch ----------------
__device__ __align__(256) float g_deg[NN];
__device__ __align__(256) int   g_cnt[NN];
__device__ __align__(256) int   g_rowptr[NN+1];
__device__ __align__(256) int   g_cursor[NN];
__device__ __align__(256) int   g_esrc[TE];
__device__ __align__(256) float g_enorm[TE];
__device__ __align__(256) float g_dinv[NN];
__device__ __align__(256) float g_agg[NN*SS*64];
__device__ __align__(256) float g_xA[NN*SS*128];
__device__ __align__(256) float g_xB[NN*SS*128];
__device__ __align__(256) float g_pooled[(size_t)NB*FLAT];          // tf32-rounded fp32 A
__device__ __align__(256) float g_Mtf[(size_t)GATE*FLAT];           // tf32-rounded fp32 Mt [j][k]
__device__ __align__(256) __nv_bfloat16 g_pwh[(size_t)FLAT*PROJ];   // pw^T hi [k][p]
__device__ __align__(256) __nv_bfloat16 g_pwl[(size_t)FLAT*PROJ];
__device__ __align__(256) __nv_bfloat16 g_wihh[(size_t)GATE*PROJ];  // wih hi [j][p]
__device__ __align__(256) __nv_bfloat16 g_wihl[(size_t)GATE*PROJ];
__device__ __align__(256) __nv_bfloat16 g_whhh[GATE*HID];
__device__ __align__(256) __nv_bfloat16 g_whhl[GATE*HID];
__device__ __align__(256) __nv_bfloat16 g_hh[NN*HID];
__device__ __align__(256) __nv_bfloat16 g_hl[NN*HID];
__device__ __align__(256) float g_fb[GATE];
__device__ __align__(256) float g_gates[(size_t)NB*GATE];
__device__ __align__(256) float g_gbuf[NN*GATE];
__device__ __align__(256) float g_h[NN*HID];
__device__ __align__(256) float g_c[NN*HID];

// ---------------- operand pre-splitting ----------------
__global__ void __launch_bounds__(256) k_pw_split(const float* __restrict__ pw) {
    __shared__ float tile[32][65];
    int k0 = blockIdx.x * 64;
    int p0 = blockIdx.y * 32;
    int tid = threadIdx.x;
    for (int u = tid; u < 512; u += 256) {
        int r = u >> 4, c4 = u & 15;
        float4 v = *(const float4*)(pw + (size_t)(p0+r)*FLAT + k0 + c4*4);
        tile[r][c4*4+0] = v.x; tile[r][c4*4+1] = v.y;
        tile[r][c4*4+2] = v.z; tile[r][c4*4+3] = v.w;
    }
    __syncthreads();
    for (int u = tid; u < 1024; u += 256) {
        int kr = u >> 4, pc = u & 15;
        float a = tile[pc*2][kr];
        float b = tile[pc*2+1][kr];
        float ha = __bfloat162float(__float2bfloat16(a));
        float hb = __bfloat162float(__float2bfloat16(b));
        size_t off = (size_t)(k0+kr)*PROJ + p0 + pc*2;
        *(uint32_t*)(g_pwh + off) = pack_bf2(ha, hb);
        *(uint32_t*)(g_pwl + off) = pack_bf2(a - ha, b - hb);
    }
}

__global__ void k_wih_split(const float* __restrict__ wih) {
    int i4 = blockIdx.x*256 + threadIdx.x;
    float4 v = ((const float4*)wih)[i4];
    float hx = __bfloat162float(__float2bfloat16(v.x));
    float hy = __bfloat162float(__float2bfloat16(v.y));
    float hz = __bfloat162float(__float2bfloat16(v.z));
    float hw = __bfloat162float(__float2bfloat16(v.w));
    ((uint2*)g_wihh)[i4] = make_uint2(pack_bf2(hx, hy), pack_bf2(hz, hw));
    ((uint2*)g_wihl)[i4] = make_uint2(pack_bf2(v.x-hx, v.y-hy), pack_bf2(v.z-hz, v.w-hw));
}

__global__ void k_whh_split(const float* __restrict__ whh) {
    int i4 = blockIdx.x*256 + threadIdx.x;
    float4 v = ((const float4*)whh)[i4];
    float hx = __bfloat162float(__float2bfloat16(v.x));
    float hy = __bfloat162float(__float2bfloat16(v.y));
    float hz = __bfloat162float(__float2bfloat16(v.z));
    float hw = __bfloat162float(__float2bfloat16(v.w));
    ((uint2*)g_whhh)[i4] = make_uint2(pack_bf2(hx, hy), pack_bf2(hz, hw));
    ((uint2*)g_whhl)[i4] = make_uint2(pack_bf2(v.x-hx, v.y-hy), pack_bf2(v.z-hz, v.w-hw));
}

// ------- fused weight: HMMA GEMM, epilogue emits tf32-rounded fp32 Mt -------
#define MT_KC    64
#define MT_AH    0
#define MT_AL    8192
#define MT_BH    16384
#define MT_BL    32768
#define MT_ST    49152
#define MT_SMEM  (3*MT_ST)

__device__ __forceinline__ void mt_load_stage(uint32_t sbase, int j0, int k0, int pt, int tid) {
#pragma unroll
    for (int h = 0; h < 2; h++) {
        int u = tid + h*256; int r = u >> 3, c = u & 7;
        uint32_t so = sbase + MT_AH + SW128(r*128 + c*16);
        cp_async16(so, (const char*)g_wihh + ((size_t)(j0+r)*PROJ + pt)*2 + c*16);
    }
#pragma unroll
    for (int h = 0; h < 2; h++) {
        int u = tid + h*256; int r = u >> 3, c = u & 7;
        uint32_t so = sbase + MT_AL + SW128(r*128 + c*16);
        cp_async16(so, (const char*)g_wihl + ((size_t)(j0+r)*PROJ + pt)*2 + c*16);
    }
#pragma unroll
    for (int h = 0; h < 4; h++) {
        int u = tid + h*256; int r = u >> 3, c = u & 7;
        uint32_t so = sbase + MT_BH + SW128(r*128 + c*16);
        cp_async16(so, (const char*)g_pwh + ((size_t)(k0+r)*PROJ + pt)*2 + c*16);
    }
#pragma unroll
    for (int h = 0; h < 4; h++) {
        int u = tid + h*256; int r = u >> 3, c = u & 7;
        uint32_t so = sbase + MT_BL + SW128(r*128 + c*16);
        cp_async16(so, (const char*)g_pwl + ((size_t)(k0+r)*PROJ + pt)*2 + c*16);
    }
}

__global__ void __launch_bounds__(256, 1) k_mt_mma() {
    extern __shared__ __align__(1024) char smem[];
    const uint32_t smem_u = smem_to_u32(smem);
    const int tid = threadIdx.x, wid = tid >> 5, lane = tid & 31;
    const int k0 = blockIdx.x * 128;
    const int j0 = blockIdx.y * 64;

    const int wm = (wid >> 2) * 32;
    const int wn = (wid & 3) * 32;
    const int a_m  = (lane & 15);
    const int a_kh = (lane >> 4) * 16;
    const int b_n  = (lane & 7) + ((lane >> 4) & 1) * 8;
    const int b_kh = ((lane >> 3) & 1) * 16;

    float acc[2][4][4];
#pragma unroll
    for (int mt = 0; mt < 2; mt++)
#pragma unroll
        for (int nt = 0; nt < 4; nt++)
#pragma unroll
            for (int q = 0; q < 4; q++) acc[mt][nt][q] = 0.f;

    mt_load_stage(smem_u,           j0, k0, 0,       tid); cp_commit();
    mt_load_stage(smem_u + MT_ST,   j0, k0, MT_KC,   tid); cp_commit();
    mt_load_stage(smem_u + 2*MT_ST, j0, k0, 2*MT_KC, tid); cp_commit();

    const int NCH = PROJ / MT_KC;
    int buf = 0;
    for (int i = 0; i < NCH; i++) {
        cp_wait<2>();
        __syncthreads();
        const uint32_t sb = smem_u + buf * MT_ST;
#pragma unroll
        for (int kk = 0; kk < 4; kk++) {
            const int kb = kk * 32;
            uint32_t ah[2][4], al[2][4];
#pragma unroll
            for (int mt = 0; mt < 2; mt++) {
                int m = wm + mt*16 + a_m;
                uint32_t off = SW128(m*128 + kb + a_kh);
                ldsm_x4(ah[mt], sb + MT_AH + off);
                ldsm_x4(al[mt], sb + MT_AL + off);
            }
            uint32_t bh[2][4], bl[2][4];
#pragma unroll
            for (int p = 0; p < 2; p++) {
                int n = wn + p*16 + b_n;
                uint32_t off = SW128(n*128 + kb + b_kh);
                ldsm_x4(bh[p], sb + MT_BH + off);
                ldsm_x4(bl[p], sb + MT_BL + off);
            }
#pragma unroll
            for (int mt = 0; mt < 2; mt++)
#pragma unroll
                for (int nt = 0; nt < 4; nt++) {
                    const uint32_t* pbh = &bh[nt >> 1][(nt & 1) * 2];
                    const uint32_t* pbl = &bl[nt >> 1][(nt & 1) * 2];
                    mma16816(acc[mt][nt], ah[mt], pbh);
                    mma16816(acc[mt][nt], ah[mt], pbl);
                    mma16816(acc[mt][nt], al[mt], pbh);
                }
        }
        __syncthreads();
        if (i + 3 < NCH) mt_load_stage(smem_u + buf * MT_ST, j0, k0, (i + 3) * MT_KC, tid);
        cp_commit();
        buf = (buf + 1 == 3) ? 0 : buf + 1;
    }

    // epilogue: Mt -> tf32-rounded fp32 [j][k]
    const int em = (lane >> 2);
    const int en = (lane & 3) * 2;
#pragma unroll
    for (int mt = 0; mt < 2; mt++)
#pragma unroll
        for (int nt = 0; nt < 4; nt++) {
            int col = k0 + wn + nt*8 + en;
#pragma unroll
            for (int half = 0; half < 2; half++) {
                int m = j0 + wm + mt*16 + em + half*8;
                uint2 v = make_uint2(f2tf32(acc[mt][nt][half*2 + 0]),
                                     f2tf32(acc[mt][nt][half*2 + 1]));
                *(uint2*)(g_Mtf + (size_t)m*FLAT + col) = v;
            }
        }
}

// ---------------- small inits / graph preprocessing ----------------
__global__ void k_init_graph() {
    int n = blockIdx.x*256 + threadIdx.x;
    if (n < NN) { g_deg[n] = 1.0f; g_cnt[n] = 1; }
}

__global__ void k_init_state() {
    int i = blockIdx.x*256 + threadIdx.x;
    if (i < NN*HID) {
        g_h[i] = 0.f; g_c[i] = 0.f;
        g_hh[i] = __float2bfloat16(0.f);
        g_hl[i] = __float2bfloat16(0.f);
    }
}

__global__ void k_edge(const int* __restrict__ ei, const float* __restrict__ ea) {
    int e = blockIdx.x*256 + threadIdx.x;
    if (e < EE) {
        int d = ei[EE + e];
        atomicAdd(&g_deg[d], ea[e]);
        atomicAdd(&g_cnt[d], 1);
    }
}

__global__ void k_scan() {
    __shared__ int sums[1024];
    int t = threadIdx.x;
    int loc[8]; int s = 0;
#pragma unroll
    for (int i = 0; i < 8; i++) { loc[i] = s; s += g_cnt[t*8 + i]; }
    sums[t] = s;
    __syncthreads();
    for (int off = 1; off < 1024; off <<= 1) {
        int v = sums[t];
        int add = (t >= off) ? sums[t - off] : 0;
        __syncthreads();
        sums[t] = v + add;
        __syncthreads();
    }
    int base = (t > 0) ? sums[t-1] : 0;
#pragma unroll
    for (int i = 0; i < 8; i++) {
        int rp = base + loc[i];
        g_rowptr[t*8 + i] = rp;
        g_cursor[t*8 + i] = rp;
    }
    if (t == 1023) g_rowptr[NN] = sums[1023];
#pragma unroll
    for (int i = 0; i < 8; i++) {
        float d = g_deg[t*8 + i];
        g_dinv[t*8 + i] = (d > 0.f) ? rsqrtf(d) : 0.f;
    }
}

__global__ void k_scatter(const int* __restrict__ ei, const float* __restrict__ ea) {
    int e = blockIdx.x*256 + threadIdx.x;
    if (e < TE) {
        int s, d; float w;
        if (e < EE) { s = ei[e]; d = ei[EE + e]; w = ea[e]; }
        else        { s = d = e - EE; w = 1.0f; }
        int pos = atomicAdd(&g_cursor[d], 1);
        g_esrc[pos]  = s;
        g_enorm[pos] = g_dinv[s] * w * g_dinv[d];
    }
}

// ---------------- GCN ----------------
__global__ void k_spmm(const float* __restrict__ xin, int sel, int L4) {
    const float4* x = (sel == 0) ? (const float4*)xin
                     : (sel == 1) ? (const float4*)g_xA : (const float4*)g_xB;
    int gid = blockIdx.x*256 + threadIdx.x;
    if (gid >= NN * L4) return;
    int n = gid / L4;
    int v = gid - n*L4;
    int e0 = g_rowptr[n], e1 = g_rowptr[n+1];
    float ax = 0.f, ay = 0.f, az = 0.f, aw = 0.f;
    for (int e = e0; e < e1; e++) {
        float w = g_enorm[e];
        int   s = g_esrc[e];
        float4 xv = x[(size_t)s*L4 + v];
        ax += w*xv.x; ay += w*xv.y; az += w*xv.z; aw += w*xv.w;
    }
    ((float4*)g_agg)[gid] = make_float4(ax, ay, az, aw);
}

template<int FI, int FO, int SELO>
__global__ void __launch_bounds__(256) k_gcn(const float* __restrict__ W, const float* __restrict__ b) {
    float* xo = (SELO == 1) ? g_xA : g_xB;
    __shared__ float Ws[FI*FO];
    __shared__ float As[32*FI];
    __shared__ float bs[FO];
    int tid = threadIdx.x;
    int r0 = blockIdx.x * 32;
    for (int i = tid; i < FI*FO; i += 256) { int o = i / FI, c = i - o*FI; Ws[c*FO + o] = W[i]; }
    for (int i = tid; i < FO; i += 256) bs[i] = b[i];
    for (int i = tid; i < 32*FI; i += 256) As[i] = g_agg[(size_t)r0*FI + i];
    __syncthreads();
    const int CG = FO / 2;
    for (int u = tid; u < 8*CG; u += 256) {
        int rg = u / CG; int cg = u - rg*CG;
        int r = rg*4, o = cg*2;
        float a00=0,a01=0,a10=0,a11=0,a20=0,a21=0,a30=0,a31=0;
#pragma unroll
        for (int c = 0; c < FI; c++) {
            float w0 = Ws[c*FO + o], w1 = Ws[c*FO + o + 1];
            float x0 = As[(r+0)*FI + c], x1 = As[(r+1)*FI + c];
            float x2 = As[(r+2)*FI + c], x3 = As[(r+3)*FI + c];
            a00 += x0*w0; a01 += x0*w1;
            a10 += x1*w0; a11 += x1*w1;
            a20 += x2*w0; a21 += x2*w1;
            a30 += x3*w0; a31 += x3*w1;
        }
        float* p0 = xo + (size_t)(r0+r  )*FO;
        float* p1 = xo + (size_t)(r0+r+1)*FO;
        float* p2 = xo + (size_t)(r0+r+2)*FO;
        float* p3 = xo + (size_t)(r0+r+3)*FO;
        p0[o] = tanhf(a00 + bs[o]); p0[o+1] = tanhf(a01 + bs[o+1]);
        p1[o] = tanhf(a10 + bs[o]); p1[o+1] = tanhf(a11 + bs[o+1]);
        p2[o] = tanhf(a20 + bs[o]); p2[o+1] = tanhf(a21 + bs[o+1]);
        p3[o] = tanhf(a30 + bs[o]); p3[o+1] = tanhf(a31 + bs[o+1]);
    }
}

// HMMA transform for big layers (FI 32/64)
template<int FI, int FO, int SELO>
__global__ void __launch_bounds__(256) k_gcn_mma(const float* __restrict__ W, const float* __restrict__ b) {
    float* xo = (SELO == 1) ? g_xA : g_xB;
    extern __shared__ __align__(1024) char smem[];
    const int SA = 128*128;
    const int SB = FO*128;
    const uint32_t uAH = smem_to_u32(smem);
    const uint32_t uAL = uAH + SA;
    const uint32_t uBH = uAH + 2*SA;
    const uint32_t uBL = uAH + 2*SA + SB;
    float* pb = (float*)(smem + 2*SA + 2*SB);
    const int tid = threadIdx.x, wid = tid >> 5, lane = tid & 31;
    const int r0 = blockIdx.x * 128;

    for (int idx = tid; idx < 128*FI/4; idx += 256) {
        int r  = idx / (FI/4);
        int c4 = idx % (FI/4);
        float4 v = *(const float4*)(g_agg + (size_t)(r0+r)*FI + c4*4);
        uint32_t sw = (uint32_t)(r*128 + c4*8) ^ ((uint32_t)(r & 7) << 4);
        float hx = __bfloat162float(__float2bfloat16(v.x));
        float hy = __bfloat162float(__float2bfloat16(v.y));
        float hz = __bfloat162float(__float2bfloat16(v.z));
        float hw = __bfloat162float(__float2bfloat16(v.w));
        *(uint32_t*)((char*)smem + sw)            = pack_bf2(hx, hy);
        *(uint32_t*)((char*)smem + sw + 4)        = pack_bf2(hz, hw);
        *(uint32_t*)((char*)smem + SA + sw)       = pack_bf2(v.x - hx, v.y - hy);
        *(uint32_t*)((char*)smem + SA + sw + 4)   = pack_bf2(v.z - hz, v.w - hw);
    }
    for (int idx = tid; idx < FO*FI/4; idx += 256) {
        int r  = idx / (FI/4);
        int c4 = idx % (FI/4);
        float4 v = *(const float4*)(W + (size_t)r*FI + c4*4);
        uint32_t sw = (uint32_t)(r*128 + c4*8) ^ ((uint32_t)(r & 7) << 4);
        float hx = __bfloat162float(__float2bfloat16(v.x));
        float hy = __bfloat162float(__float2bfloat16(v.y));
        float hz = __bfloat162float(__float2bfloat16(v.z));
        float hw = __bfloat162float(__float2bfloat16(v.w));
        *(uint32_t*)((char*)smem + 2*SA + sw)          = pack_bf2(hx, hy);
        *(uint32_t*)((char*)smem + 2*SA + sw + 4)      = pack_bf2(hz, hw);
        *(uint32_t*)((char*)smem + 2*SA + SB + sw)     = pack_bf2(v.x - hx, v.y - hy);
        *(uint32_t*)((char*)smem + 2*SA + SB + sw + 4) = pack_bf2(v.z - hz, v.w - hw);
    }
    for (int i = tid; i < FO; i += 256) pb[i] = b[i];
    __syncthreads();

    constexpr int NT  = (FO == 128) ? 8 : 4;
    constexpr int NPT = NT / 2;
    const int wm = (wid >> 1) * 32;
    const int wn = (wid & 1) * (FO / 2);
    const int a_m  = (lane & 15);
    const int a_kh = (lane >> 4) * 16;
    const int b_n  = (lane & 7) + ((lane >> 4) & 1) * 8;
    const int b_kh = ((lane >> 3) & 1) * 16;

    float acc[2][NT][4];
#pragma unroll
    for (int mt = 0; mt < 2; mt++)
#pragma unroll
        for (int nt = 0; nt < NT; nt++)
#pragma unroll
            for (int q = 0; q < 4; q++) acc[mt][nt][q] = 0.f;

#pragma unroll
    for (int kk = 0; kk < FI/16; kk++) {
        const int kb = kk * 32;
        uint32_t ah[2][4], al[2][4];
#pragma unroll
        for (int mt = 0; mt < 2; mt++) {
            int m = wm + mt*16 + a_m;
            uint32_t off = (uint32_t)(m*128 + kb + a_kh) ^ ((uint32_t)(m & 7) << 4);
            ldsm_x4(ah[mt], uAH + off);
            ldsm_x4(al[mt], uAL + off);
        }
        uint32_t bh[NPT][4], bl[NPT][4];
#pragma unroll
        for (int p = 0; p < NPT; p++) {
            int n = wn + p*16 + b_n;
            uint32_t off = (uint32_t)(n*128 + kb + b_kh) ^ ((uint32_t)(n & 7) << 4);
            ldsm_x4(bh[p], uBH + off);
            ldsm_x4(bl[p], uBL + off);
        }
#pragma unroll
        for (int mt = 0; mt < 2; mt++)
#pragma unroll
            for (int nt = 0; nt < NT; nt++) {
                const uint32_t* pbh = &bh[nt >> 1][(nt & 1) * 2];
                const uint32_t* pbl = &bl[nt >> 1][(nt & 1) * 2];
                mma16816(acc[mt][nt], ah[mt], pbh);
                mma16816(acc[mt][nt], ah[mt], pbl);
                mma16816(acc[mt][nt], al[mt], pbh);
            }
    }

    const int em = (lane >> 2);
    const int en = (lane & 3) * 2;
#pragma unroll
    for (int mt = 0; mt < 2; mt++)
#pragma unroll
        for (int nt = 0; nt < NT; nt++) {
            int col = wn + nt*8 + en;
            int m   = r0 + wm + mt*16 + em;
            float b0 = pb[col], b1 = pb[col+1];
            float2 v0 = make_float2(tanhf(acc[mt][nt][0] + b0), tanhf(acc[mt][nt][1] + b1));
            float2 v1 = make_float2(tanhf(acc[mt][nt][2] + b0), tanhf(acc[mt][nt][3] + b1));
            *(float2*)(xo + (size_t)m * FO + col)       = v0;
            *(float2*)(xo + (size_t)(m + 8) * FO + col) = v1;
        }
}

// ------- conv+pool: per-node scalar; writes tf32-rounded fp32 pooled -------
__global__ void k_convpool(const float* __restrict__ cw, const float* __restrict__ cb) {
    __shared__ __align__(16) float xs[SS*YC];
    __shared__ float cws[10], cbs[2];
    int n = blockIdx.x;
    int tid = threadIdx.x;
    const float4* src = (const float4*)(g_xA + (size_t)n*SS*YC);
    for (int i = tid; i < SS*YC/4; i += 256) ((float4*)xs)[i] = src[i];
    if (tid < 10) cws[tid] = cw[tid];
    if (tid < 2)  cbs[tid] = cb[tid];
    __syncthreads();
#pragma unroll
    for (int w = 0; w < NWIN; w++) {
        const float* win = xs + w*YC;
        size_t obase = (size_t)(n*NWIN + w)*FLAT;
        for (int i = tid; i < FLAT; i += 256) {
            int f = i / 1280;
            int q = i - f*1280;
            int p0 = q*2;
            float v0 = cbs[f], v1 = cbs[f];
#pragma unroll
            for (int k = 0; k < 5; k++) {
                int p = p0 + k - 2;
                if (p >= 0 && p < FLAT) v0 += win[p] * cws[f*5 + k];
                p += 1;
                if (p >= 0 && p < FLAT) v1 += win[p] * cws[f*5 + k];
            }
            ((uint32_t*)g_pooled)[obase + i] = f2tf32(fmaxf(v0, v1));
        }
    }
}

// ------- fused bias: one warp per output j -------
__global__ void __launch_bounds__(256) k_fb(const float* __restrict__ wih, const float* __restrict__ pb,
                     const float* __restrict__ bih, const float* __restrict__ bhh) {
    int wix = (blockIdx.x*256 + threadIdx.x) >> 5;
    int lane = threadIdx.x & 31;
    if (wix >= GATE) return;
    const float* row = wih + (size_t)wix*PROJ;
    float acc = 0.f;
#pragma unroll 8
    for (int p = lane; p < PROJ; p += 32) acc += row[p] * pb[p];
#pragma unroll
    for (int o = 16; o > 0; o >>= 1) acc += __shfl_xor_sync(0xFFFFFFFFu, acc, o);
    if (lane == 0) g_fb[wix] = acc + bih[wix] + bhh[wix];
}

// ============ gates GEMM: single-pass TF32, KC=64, 3-stage ============
// Stage layout: A0(k0-31) A1(k32-63) B0 B1, each 128 rows x 32 tf32 (128B rows, SW128).
#define GK_KC    64
#define GK_NCH   (FLAT/GK_KC)
#define ST_A0    0
#define ST_A1    16384
#define ST_B0    32768
#define ST_B1    49152
#define ST_SIZE  65536
#define GK_SMEM  (3*ST_SIZE + 512)

__device__ __forceinline__ void gk_load_stage(uint32_t sbase, int m0, int j0, int kt, int tid) {
#pragma unroll
    for (int h = 0; h < 16; h++) {
        int tile = h >> 2;                 // 0 A0, 1 A1, 2 B0, 3 B1
        int u    = tid + (h & 3) * 256;    // 0..1023
        int r    = u >> 3;
        int c    = u & 7;
        uint32_t so = sbase + tile*16384 + SW128(r*128 + c*16);
        const float* gp = (tile < 2)
            ? g_pooled + (size_t)(m0 + r) * FLAT + kt + (tile & 1)*32 + c*4
            : g_Mtf    + (size_t)(j0 + r) * FLAT + kt + (tile & 1)*32 + c*4;
        cp_async16(so, gp);
    }
}

__global__ void __launch_bounds__(256, 1) k_gates_tf32() {
    extern __shared__ __align__(1024) char smem[];
    const uint32_t smem_u = smem_to_u32(smem);
    float* fbs = (float*)(smem + 3*ST_SIZE);
    const int tid = threadIdx.x;
    const int wid = tid >> 5;
    const int lane = tid & 31;
    const int j0 = blockIdx.x * 128;
    const int m0 = blockIdx.y * 128;
    const int wm = (wid >> 1) * 32;
    const int wn = (wid & 1) * 64;

    if (tid < 128) fbs[tid] = g_fb[j0 + tid];

    float acc[2][8][4];
#pragma unroll
    for (int mt = 0; mt < 2; mt++)
#pragma unroll
        for (int nt = 0; nt < 8; nt++)
#pragma unroll
            for (int q = 0; q < 4; q++) acc[mt][nt][q] = 0.f;

    gk_load_stage(smem_u,             m0, j0, 0,        tid); cp_commit();
    gk_load_stage(smem_u + ST_SIZE,   m0, j0, GK_KC,    tid); cp_commit();
    gk_load_stage(smem_u + 2*ST_SIZE, m0, j0, 2*GK_KC,  tid); cp_commit();

    // ldsm lane mapping for tf32 fragments (a0..a3 / b0,b1 per n16)
    const int fr = (lane & 7) + ((lane >> 3) & 1) * 8;   // row within 16-row tile pair
    const int fk = (lane >> 4) * 16;                     // 0 or 16 bytes (k0-3 / k4-7)

    int buf = 0;
    for (int i = 0; i < GK_NCH; i++) {
        cp_wait<2>();
        __syncthreads();
        const uint32_t sb = smem_u + buf * ST_SIZE;

#pragma unroll
        for (int kk = 0; kk < 8; kk++) {               // 8 k8-steps per KC=64 chunk
            const int sub = kk >> 2;                    // which 32-k sub-array
            const int kb  = (kk & 3) * 32;              // byte offset within 128B row
            const uint32_t aB = sb + (sub ? ST_A1 : ST_A0);
            const uint32_t bB = sb + (sub ? ST_B1 : ST_B0);
            uint32_t af[2][4];
#pragma unroll
            for (int mt = 0; mt < 2; mt++) {
                int m = wm + mt*16 + fr;
                ldsm_x4(af[mt], aB + SW128(m*128 + kb + fk));
            }
            uint32_t bf[4][4];
#pragma unroll
            for (int p = 0; p < 4; p++) {
                int n = wn + p*16 + fr;
                ldsm_x4(bf[p], bB + SW128(n*128 + kb + fk));
            }
#pragma unroll
            for (int mt = 0; mt < 2; mt++)
#pragma unroll
                for (int nt = 0; nt < 8; nt++) {
                    const int p = nt >> 1, o = nt & 1;
                    mma16808_tf32(acc[mt][nt], af[mt], bf[p][o], bf[p][o + 2]);
                }
        }
        __syncthreads();
        if (i + 3 < GK_NCH) {
            gk_load_stage(smem_u + buf * ST_SIZE, m0, j0, (i + 3) * GK_KC, tid);
        }
        cp_commit();
        buf = (buf + 1 == 3) ? 0 : buf + 1;
    }

    const int em = (lane >> 2);
    const int en = (lane & 3) * 2;
#pragma unroll
    for (int mt = 0; mt < 2; mt++) {
#pragma unroll
        for (int nt = 0; nt < 8; nt++) {
            int nl = wn + nt*8 + en;
            int m  = m0 + wm + mt*16 + em;
            float f0 = fbs[nl], f1 = fbs[nl + 1];
            float2 v0 = make_float2(acc[mt][nt][0] + f0, acc[mt][nt][1] + f1);
            float2 v1 = make_float2(acc[mt][nt][2] + f0, acc[mt][nt][3] + f1);
            *(float2*)(g_gates + (size_t)m * GATE + j0 + nl)       = v0;
            *(float2*)(g_gates + (size_t)(m + 8) * GATE + j0 + nl) = v1;
        }
    }
}

// ---------------- LSTM: HMMA recurrent gemm ----------------
#define LG_SMEM (2*16384 + 2*32768)
__global__ void __launch_bounds__(256) k_lstm_mma(int t) {
    extern __shared__ __align__(1024) char smem[];
    const uint32_t uAH = smem_to_u32(smem);
    const uint32_t uAL = uAH + 16384;
    const uint32_t uBH = uAH + 32768;
    const uint32_t uBL = uAH + 65536;
    const int tid = threadIdx.x, wid = tid >> 5, lane = tid & 31;
    const int j0 = blockIdx.x * 128;
    const int n0 = blockIdx.y * 64;

    for (int u = tid; u < 1024; u += 256) {
        int r = u >> 4, c8 = u & 15;
        int row = r + 64*(c8 >> 3);
        uint32_t sw = (uint32_t)(row*128 + (c8 & 7)*16) ^ ((uint32_t)(row & 7) << 4);
        *(uint4*)((char*)smem + sw)         = *(const uint4*)(g_hh + (size_t)(n0+r)*HID + c8*8);
        *(uint4*)((char*)smem + 16384 + sw) = *(const uint4*)(g_hl + (size_t)(n0+r)*HID + c8*8);
    }
    for (int u = tid; u < 2048; u += 256) {
        int r = u >> 4, c8 = u & 15;
        int row = r + 128*(c8 >> 3);
        uint32_t sw = (uint32_t)(row*128 + (c8 & 7)*16) ^ ((uint32_t)(row & 7) << 4);
        *(uint4*)((char*)smem + 32768 + sw) = *(const uint4*)(g_whhh + (size_t)(j0+r)*HID + c8*8);
        *(uint4*)((char*)smem + 65536 + sw) = *(const uint4*)(g_whhl + (size_t)(j0+r)*HID + c8*8);
    }
    __syncthreads();

    const int wm = (wid >> 2) * 32;
    const int wn = (wid & 3) * 32;
    const int a_m  = (lane & 15);
    const int a_kh = (lane >> 4) * 16;
    const int b_n  = (lane & 7) + ((lane >> 4) & 1) * 8;
    const int b_kh = ((lane >> 3) & 1) * 16;

    float acc[2][4][4];
#pragma unroll
    for (int mt = 0; mt < 2; mt++)
#pragma unroll
        for (int nt = 0; nt < 4; nt++)
#pragma unroll
            for (int q = 0; q < 4; q++) acc[mt][nt][q] = 0.f;

#pragma unroll
    for (int kk = 0; kk < 8; kk++) {
        const int half = kk >> 2;
        const int kb = (kk & 3) * 32;
        uint32_t ah[2][4], al[2][4];
#pragma unroll
        for (int mt = 0; mt < 2; mt++) {
            int m = wm + mt*16 + a_m;
            int row = m + 64*half;
            uint32_t off = (uint32_t)(row*128 + kb + a_kh) ^ ((uint32_t)(row & 7) << 4);
            ldsm_x4(ah[mt], uAH + off);
            ldsm_x4(al[mt], uAL + off);
        }
        uint32_t bh[2][4], bl[2][4];
#pragma unroll
        for (int p = 0; p < 2; p++) {
            int nj = wn + p*16 + b_n;
            int row = nj + 128*half;
            uint32_t off = (uint32_t)(row*128 + kb + b_kh) ^ ((uint32_t)(row & 7) << 4);
            ldsm_x4(bh[p], uBH + off);
            ldsm_x4(bl[p], uBL + off);
        }
#pragma unroll
        for (int mt = 0; mt < 2; mt++)
#pragma unroll
            for (int nt = 0; nt < 4; nt++) {
                const uint32_t* pbh = &bh[nt >> 1][(nt & 1) * 2];
                const uint32_t* pbl = &bl[nt >> 1][(nt & 1) * 2];
                mma16816(acc[mt][nt], ah[mt], pbh);
                mma16816(acc[mt][nt], ah[mt], pbl);
                mma16816(acc[mt][nt], al[mt], pbh);
            }
    }

    const int em = (lane >> 2);
    const int en = (lane & 3) * 2;
#pragma unroll
    for (int mt = 0; mt < 2; mt++)
#pragma unroll
        for (int nt = 0; nt < 4; nt++) {
            int jj = j0 + wn + nt*8 + en;
#pragma unroll
            for (int half = 0; half < 2; half++) {
                int n = n0 + wm + mt*16 + em + half*8;
                float2 gx = *(const float2*)(g_gates + ((size_t)n*4 + t)*GATE + jj);
                float2 v = make_float2(acc[mt][nt][half*2+0] + gx.x,
                                       acc[mt][nt][half*2+1] + gx.y);
                *(float2*)(g_gbuf + (size_t)n*GATE + jj) = v;
            }
        }
}

__device__ __forceinline__ float sigf(float x) { return 1.0f / (1.0f + expf(-x)); }

__global__ void k_lstm_point() {
    int idx = blockIdx.x*256 + threadIdx.x;
    if (idx < NN*HID) {
        int n = idx >> 7, j = idx & 127;
        const float* g = g_gbuf + (size_t)n*GATE;
        float gi = g[j], gf = g[HID + j], gg = g[2*HID + j], go = g[3*HID + j];
        float c = sigf(gf) * g_c[idx] + sigf(gi) * tanhf(gg);
        g_c[idx] = c;
        float h = sigf(go) * tanhf(c);
        g_h[idx] = h;
        __nv_bfloat16 hb = __float2bfloat16(h);
        g_hh[idx] = hb;
        g_hl[idx] = __float2bfloat16(h - __bfloat162float(hb));
    }
}

// ---------------- output head ----------------
__global__ void k_out(const float* __restrict__ ow, const float* __restrict__ ob,
                      float* __restrict__ out) {
    int idx = blockIdx.x*256 + threadIdx.x;
    if (idx < NN*LBL) {
        int n = idx / LBL, l = idx - n*LBL;
        float acc = ob[l];
        const float* hr = g_h + (size_t)n*HID;
        const float* wr = ow + (size_t)l*HID;
#pragma unroll 8
        for (int k = 0; k < HID; k++) acc += hr[k]*wr[k];
        out[idx] = acc;
    }
}

// ---------------- launch ----------------
extern "C" void kernel_launch(void* const* d_in, const int* in_sizes, int n_in,
                              void* d_out, int out_size) {
    const float* inputs = (const float*)d_in[0];
    const int*   ei     = (const int*)  d_in[1];
    const float* ea     = (const float*)d_in[2];
    const float* W1 = (const float*)d_in[3];  const float* b1 = (const float*)d_in[4];
    const float* W2 = (const float*)d_in[5];  const float* b2 = (const float*)d_in[6];
    const float* W3 = (const float*)d_in[7];  const float* b3 = (const float*)d_in[8];
    const float* W4 = (const float*)d_in[9];  const float* b4 = (const float*)d_in[10];
    const float* W5 = (const float*)d_in[11]; const float* b5 = (const float*)d_in[12];
    const float* cw  = (const float*)d_in[13]; const float* cb  = (const float*)d_in[14];
    const float* pw  = (const float*)d_in[15]; const float* pb  = (const float*)d_in[16];
    const float* wih = (const float*)d_in[17]; const float* whh = (const float*)d_in[18];
    const float* bih = (const float*)d_in[19]; const float* bhh = (const float*)d_in[20];
    const float* ow  = (const float*)d_in[21]; const float* ob  = (const float*)d_in[22];
    float* out = (float*)d_out;

    const int SMEM_GCN4 = 2*16384 + 2*64*128  + 256;
    const int SMEM_GCN5 = 2*16384 + 2*128*128 + 512;
    cudaFuncSetAttribute(k_gates_tf32, cudaFuncAttributeMaxDynamicSharedMemorySize, GK_SMEM);
    cudaFuncSetAttribute(k_gcn_mma<32,64,2>,  cudaFuncAttributeMaxDynamicSharedMemorySize, SMEM_GCN4);
    cudaFuncSetAttribute(k_gcn_mma<64,128,1>, cudaFuncAttributeMaxDynamicSharedMemorySize, SMEM_GCN5);
    cudaFuncSetAttribute(k_mt_mma,  cudaFuncAttributeMaxDynamicSharedMemorySize, MT_SMEM);
    cudaFuncSetAttribute(k_lstm_mma, cudaFuncAttributeMaxDynamicSharedMemorySize, LG_SMEM);

    static cudaStream_t s2 = nullptr;
    static cudaEvent_t evF = nullptr, evJ = nullptr;
    if (s2 == nullptr) {
        cudaStreamCreateWithFlags(&s2, cudaStreamNonBlocking);
        cudaEventCreateWithFlags(&evF, cudaEventDisableTiming);
        cudaEventCreateWithFlags(&evJ, cudaEventDisableTiming);
    }

    // fork: weight-prep chain on s2
    cudaEventRecord(evF, 0);
    cudaStreamWaitEvent(s2, evF, 0);
    k_pw_split<<<dim3(FLAT/64, PROJ/32), 256, 0, s2>>>(pw);
    k_wih_split<<<GATE*PROJ/4/256, 256, 0, s2>>>(wih);
    k_whh_split<<<GATE*HID/4/256, 256, 0, s2>>>(whh);
    k_mt_mma<<<dim3(FLAT/128, GATE/64), 256, MT_SMEM, s2>>>();
    k_fb<<<GATE/8, 256, 0, s2>>>(wih, pb, bih, bhh);
    cudaEventRecord(evJ, s2);

    // main chain
    k_init_graph<<<32, 256>>>();
    k_init_state<<<4096, 256>>>();
    k_edge<<<EE/256, 256>>>(ei, ea);
    k_scan<<<1, 1024>>>();
    k_scatter<<<(TE + 255)/256, 256>>>(ei, ea);

    k_spmm<<<(NN*24  + 255)/256, 256>>>(inputs, 0, 24);
    k_gcn<4, 8, 1><<<6144, 256>>>(W1, b1);
    k_spmm<<<(NN*48  + 255)/256, 256>>>(nullptr, 1, 48);
    k_gcn<8, 16, 2><<<6144, 256>>>(W2, b2);
    k_spmm<<<(NN*96  + 255)/256, 256>>>(nullptr, 2, 96);
    k_gcn<16, 32, 1><<<6144, 256>>>(W3, b3);
    k_spmm<<<(NN*192 + 255)/256, 256>>>(nullptr, 1, 192);
    k_gcn_mma<32, 64, 2><<<1536, 256, SMEM_GCN4>>>(W4, b4);
    k_spmm<<<(NN*384 + 255)/256, 256>>>(nullptr, 2, 384);
    k_gcn_mma<64, 128, 1><<<1536, 256, SMEM_GCN5>>>(W5, b5);

    k_convpool<<<NN, 256>>>(cw, cb);

    cudaStreamWaitEvent(0, evJ, 0);

    k_gates_tf32<<<dim3(4, 256), 256, GK_SMEM>>>();

    for (int t = 0; t < NWIN; t++) {
        k_lstm_mma<<<dim3(4, 128), 256, LG_SMEM>>>(t);
        k_lstm_point<<<4096, 256>>>();
    }

    k_out<<<(NN*LBL + 255)/256, 256>>>(ow, ob, out);
}